// round 3
// baseline (speedup 1.0000x reference)
#include <cuda_runtime.h>
#include <math.h>
#include <float.h>

#define B_TOT   16384
#define NVOX    50000
#define MVIEW   12
#define FDIM    256
#define FAUG    272       // FDIM + 16 (extrinsics)
#define HEADS   8
#define QDIM    512       // HEADS*DK
#define ODIM    512       // HEADS*DV
#define PE3     24        // PE_ORDER*3
#define CDIM    2176      // HEADS*FAUG
#define VPB     8         // voxels per CTA in fused attn

// ---------------- scratch (static device memory; no allocation) ----------------
__device__ unsigned int g_minb[3];
__device__ unsigned int g_maxb[3];
__device__ float g_pe[B_TOT * PE3];                      // 1.5 MB
__device__ float g_C2[PE3 * CDIM];                       // 209 KB
__device__ float g_mixed[(size_t)B_TOT * HEADS * FDIM];  // 128 MB

// ---------------- packed f32x2 helpers ----------------
__device__ __forceinline__ void ffma2(unsigned long long& d,
                                      unsigned long long a,
                                      unsigned long long b) {
    asm("fma.rn.f32x2 %0, %1, %2, %0;" : "+l"(d) : "l"(a), "l"(b));
}
__device__ __forceinline__ unsigned long long pack2(float x, float y) {
    unsigned long long r;
    asm("mov.b64 %0, {%1, %2};" : "=l"(r) : "f"(x), "f"(y));
    return r;
}
__device__ __forceinline__ float2 unpack2(unsigned long long v) {
    float2 r;
    asm("mov.b64 {%0, %1}, %2;" : "=f"(r.x), "=f"(r.y) : "l"(v));
    return r;
}

// Ordered-uint encoding so unsigned atomicMin/Max implements float min/max.
__device__ __forceinline__ unsigned int fenc(float f) {
    unsigned int u = __float_as_uint(f);
    return (u & 0x80000000u) ? ~u : (u | 0x80000000u);
}
__device__ __forceinline__ float fdec(unsigned int u) {
    u = (u & 0x80000000u) ? (u & 0x7FFFFFFFu) : ~u;
    return __uint_as_float(u);
}

// ---------------- K0: init min/max ----------------
__global__ void k_init() {
    int t = threadIdx.x;
    if (t < 3) { g_minb[t] = 0xFFFFFFFFu; g_maxb[t] = 0u; }
}

// ---------------- K1: per-component min/max over voxels ----------------
__global__ void k_minmax(const float* __restrict__ vox) {
    float mn[3] = {FLT_MAX, FLT_MAX, FLT_MAX};
    float mx[3] = {-FLT_MAX, -FLT_MAX, -FLT_MAX};
    for (int r = blockIdx.x * blockDim.x + threadIdx.x; r < NVOX;
         r += gridDim.x * blockDim.x) {
        #pragma unroll
        for (int c = 0; c < 3; c++) {
            float v = vox[r * 3 + c];
            mn[c] = fminf(mn[c], v);
            mx[c] = fmaxf(mx[c], v);
        }
    }
    #pragma unroll
    for (int c = 0; c < 3; c++) {
        #pragma unroll
        for (int o = 16; o > 0; o >>= 1) {
            mn[c] = fminf(mn[c], __shfl_xor_sync(0xffffffffu, mn[c], o));
            mx[c] = fmaxf(mx[c], __shfl_xor_sync(0xffffffffu, mx[c], o));
        }
    }
    if ((threadIdx.x & 31) == 0) {
        #pragma unroll
        for (int c = 0; c < 3; c++) {
            atomicMin(&g_minb[c], fenc(mn[c]));
            atomicMax(&g_maxb[c], fenc(mx[c]));
        }
    }
}

// ---------------- K2: pe[b, 24] = sinusoidal PE of normalized xyz ----------------
__global__ void __launch_bounds__(256) k_pe(const int* __restrict__ vidx,
                                            const float* __restrict__ vox) {
    int b = blockIdx.x * 256 + threadIdx.x;
    if (b >= B_TOT) return;
    float mn[3], rng[3];
    #pragma unroll
    for (int c = 0; c < 3; c++) {
        float lo = fdec(g_minb[c]);
        float hi = fdec(g_maxb[c]);
        mn[c] = lo; rng[c] = hi - lo;
    }
    int idx = vidx[b];
    float xn[3];
    #pragma unroll
    for (int c = 0; c < 3; c++)
        xn[c] = (vox[idx * 3 + c] - mn[c]) / rng[c] - 0.5f;
    float fr = 1.0f;
    float* dst = g_pe + (size_t)b * PE3;
    #pragma unroll
    for (int p = 0; p < 8; p++) {
        dst[p * 3 + 0] = sinf(xn[0] * fr);
        dst[p * 3 + 1] = sinf(xn[1] * fr);
        dst[p * 3 + 2] = sinf(xn[2] * fr);
        fr *= 2.0f;
    }
}

// ---------------- K3: C2[j, h*272+f] = sum_d Wq[j, h*64+d] * Wk[f, h*64+d] --------
__global__ void __launch_bounds__(256) k_C2(const float* __restrict__ Wq,
                                            const float* __restrict__ Wk) {
    int i = blockIdx.x * 256 + threadIdx.x;
    if (i >= PE3 * CDIM) return;
    int j = i / CDIM;
    int col = i - j * CDIM;
    int h = col / FAUG;
    int f = col - h * FAUG;
    const float4* wq = (const float4*)(Wq + j * QDIM + h * 64);
    const float4* wk = (const float4*)(Wk + (size_t)f * QDIM + h * 64);
    float a0 = 0.f, a1 = 0.f, a2 = 0.f, a3 = 0.f;
    #pragma unroll
    for (int d = 0; d < 16; d++) {
        float4 q = wq[d], k = wk[d];
        a0 += q.x * k.x; a1 += q.y * k.y;
        a2 += q.z * k.z; a3 += q.w * k.w;
    }
    g_C2[i] = (a0 + a1) + (a2 + a3);
}

// ---------------- K4 (fused): qW on-the-fly + gather + logits + softmax + mix ------
// 8 voxels per CTA, 256 threads. Dynamic smem ≈ 106 KB -> 2 CTAs/SM.
//   smem layout (floats):
//   sqw  [VPB][CDIM]   17408
//   c2S  [PE3][256]     6144
//   sf   [MVIEW][FDIM]  3072
//   spe  [VPB][PE3]      192
//   sp   [HEADS][MVIEW]   96
//   smask[VPB][MVIEW]     96
//   scam [VPB][MVIEW]     96 (ints)
//   sidx [VPB]             8 (ints)
#define ATTN_F_SQW   0
#define ATTN_F_C2S   17408
#define ATTN_F_SF    23552
#define ATTN_F_SPE   26624
#define ATTN_F_SP    26816
#define ATTN_F_MASK  26912
#define ATTN_F_CAM   27008
#define ATTN_F_IDX   27104
#define ATTN_SMEM    ((27104 + 8) * 4)

__global__ void __launch_bounds__(256) k_attn2(const int* __restrict__ vidx,
                                               const float* __restrict__ feats_g,
                                               const float* __restrict__ scores_g,
                                               const int* __restrict__ camids,
                                               const float* __restrict__ extr) {
    extern __shared__ float smem[];
    float* sqw   = smem + ATTN_F_SQW;    // [VPB][CDIM]
    float* c2S   = smem + ATTN_F_C2S;    // [PE3][256]
    float* sf    = smem + ATTN_F_SF;     // [MVIEW][FDIM]
    float* spe   = smem + ATTN_F_SPE;    // [VPB][PE3]
    float* sp    = smem + ATTN_F_SP;     // [HEADS][MVIEW]
    float* smask = smem + ATTN_F_MASK;   // [VPB][MVIEW]
    int*   scam  = (int*)(smem + ATTN_F_CAM);
    int*   sidx  = (int*)(smem + ATTN_F_IDX);

    int b0 = blockIdx.x * VPB;
    int tid = threadIdx.x;
    int w = tid >> 5, lane = tid & 31;

    if (tid < VPB) sidx[tid] = vidx[b0 + tid];
    __syncthreads();
    if (tid < VPB * PE3)
        spe[tid] = g_pe[(size_t)b0 * PE3 + tid];
    if (tid < VPB * MVIEW) {
        int v = tid / MVIEW, m = tid - v * MVIEW;
        float s = scores_g[(size_t)sidx[v] * MVIEW + m];
        smask[tid] = (s < 0.0f) ? -1e30f : 0.0f;
        scam[tid] = camids[(size_t)sidx[v] * MVIEW + m];
    }
    __syncthreads();

    // ---- phase 1: qW[v] = pe[v] @ C2, warp w handles voxel w ----
    unsigned long long pe2[PE3];
    #pragma unroll
    for (int j = 0; j < PE3; j++) {
        float p = spe[w * PE3 + j];
        pe2[j] = pack2(p, p);
    }
    for (int panel = 0; panel < 9; panel++) {
        int cbase = panel * 256;
        int ncols = min(256, CDIM - cbase);   // 256 or 128
        __syncthreads();
        if (tid < ncols) {
            #pragma unroll
            for (int r = 0; r < PE3; r++)
                c2S[r * 256 + tid] = g_C2[r * CDIM + cbase + tid];
        }
        __syncthreads();
        for (int ch = 0; ch < ncols; ch += 128) {
            int c = ch + lane * 4;
            unsigned long long acc0 = 0ull, acc1 = 0ull;
            #pragma unroll
            for (int j = 0; j < PE3; j++) {
                ulonglong2 cc = *(const ulonglong2*)&c2S[j * 256 + c];
                ffma2(acc0, pe2[j], cc.x);
                ffma2(acc1, pe2[j], cc.y);
            }
            *(ulonglong2*)&sqw[w * CDIM + cbase + c] = make_ulonglong2(acc0, acc1);
        }
    }

    // ---- phase 2: per-voxel attention ----
    for (int v = 0; v < VPB; v++) {
        __syncthreads();   // sqw ready (v=0) / previous mix done (v>0)
        const float4* fsrc = (const float4*)(feats_g + (size_t)sidx[v] * MVIEW * FDIM);
        float4* fdst = (float4*)sf;
        #pragma unroll
        for (int i = 0; i < 3; i++) fdst[tid + i * 256] = fsrc[tid + i * 256];
        __syncthreads();

        // warp w = head w
        const float* qv = sqw + v * CDIM + w * FAUG;
        float lg[MVIEW];
        #pragma unroll
        for (int m = 0; m < MVIEW; m++) {
            float s = 0.0f;
            #pragma unroll
            for (int u = 0; u < 8; u++) {
                int t = lane + u * 32;
                s += sf[m * FDIM + t] * qv[t];
            }
            if (lane < 16)
                s += extr[scam[v * MVIEW + m] * 16 + lane] * qv[256 + lane];
            #pragma unroll
            for (int o = 16; o > 0; o >>= 1)
                s += __shfl_xor_sync(0xffffffffu, s, o);
            lg[m] = s * 0.125f + smask[v * MVIEW + m];
        }
        if (lane == 0) {
            float mx = -FLT_MAX;
            #pragma unroll
            for (int m = 0; m < MVIEW; m++) mx = fmaxf(mx, lg[m]);
            float e[MVIEW], sum = 0.0f;
            #pragma unroll
            for (int m = 0; m < MVIEW; m++) { e[m] = expf(lg[m] - mx); sum += e[m]; }
            float inv = 1.0f / sum;
            #pragma unroll
            for (int m = 0; m < MVIEW; m++) sp[w * MVIEW + m] = e[m] * inv;
        }
        __syncthreads();

        // mixed[b0+v, h, tid] = sum_m p[h,m] * feats[m, tid]
        float fv[MVIEW];
        #pragma unroll
        for (int m = 0; m < MVIEW; m++) fv[m] = sf[m * FDIM + tid];
        #pragma unroll
        for (int h = 0; h < HEADS; h++) {
            float acc = 0.0f;
            #pragma unroll
            for (int m = 0; m < MVIEW; m++) acc += sp[h * MVIEW + m] * fv[m];
            g_mixed[(size_t)(b0 + v) * (HEADS * FDIM) + h * FDIM + tid] = acc;
        }
    }
}

// ---------------- K5: out[b, h*64+j] = mixed[b,h,:] @ Wv_h (FFMA2) ----------------
#define OUT_SMEM ((256 * 64 + 32 * 132) * 4)
__global__ void __launch_bounds__(256) k_out(const float* __restrict__ Wv,
                                             float* __restrict__ out) {
    extern __shared__ float sm[];
    float* WvS = sm;                 // [256][64]
    float* As  = sm + 256 * 64;      // [32][132] (k-major, padded)
    int h = blockIdx.y;
    int b0 = blockIdx.x * 128;
    int tid = threadIdx.x;

    for (int i = tid; i < 256 * 16; i += 256) {
        int k = i >> 4, c4 = (i & 15) * 4;
        *(float4*)&WvS[k * 64 + c4] = *(const float4*)&Wv[(size_t)k * ODIM + h * 64 + c4];
    }

    int ty = tid >> 4, tx = tid & 15;
    unsigned long long acc[4][4] = {};   // 4 row-pairs x 4 cols, packed over rows

    for (int k0 = 0; k0 < FDIM; k0 += 32) {
        __syncthreads();
        for (int i = tid; i < 128 * 8; i += 256) {
            int row = i >> 3, k4 = (i & 7) * 4;
            float4 v = *(const float4*)&g_mixed[(size_t)(b0 + row) * (HEADS * FDIM)
                                                + h * FDIM + k0 + k4];
            As[(k4 + 0) * 132 + row] = v.x;
            As[(k4 + 1) * 132 + row] = v.y;
            As[(k4 + 2) * 132 + row] = v.z;
            As[(k4 + 3) * 132 + row] = v.w;
        }
        __syncthreads();
        #pragma unroll
        for (int kk = 0; kk < 32; kk++) {
            ulonglong2 A0 = *(ulonglong2*)&As[kk * 132 + ty * 8];
            ulonglong2 A1 = *(ulonglong2*)&As[kk * 132 + ty * 8 + 4];
            float4 b4 = *(float4*)&WvS[(k0 + kk) * 64 + tx * 4];
            unsigned long long bb0 = pack2(b4.x, b4.x);
            unsigned long long bb1 = pack2(b4.y, b4.y);
            unsigned long long bb2 = pack2(b4.z, b4.z);
            unsigned long long bb3 = pack2(b4.w, b4.w);
            ffma2(acc[0][0], A0.x, bb0); ffma2(acc[0][1], A0.x, bb1);
            ffma2(acc[0][2], A0.x, bb2); ffma2(acc[0][3], A0.x, bb3);
            ffma2(acc[1][0], A0.y, bb0); ffma2(acc[1][1], A0.y, bb1);
            ffma2(acc[1][2], A0.y, bb2); ffma2(acc[1][3], A0.y, bb3);
            ffma2(acc[2][0], A1.x, bb0); ffma2(acc[2][1], A1.x, bb1);
            ffma2(acc[2][2], A1.x, bb2); ffma2(acc[2][3], A1.x, bb3);
            ffma2(acc[3][0], A1.y, bb0); ffma2(acc[3][1], A1.y, bb1);
            ffma2(acc[3][2], A1.y, bb2); ffma2(acc[3][3], A1.y, bb3);
        }
    }
    #pragma unroll
    for (int ip = 0; ip < 4; ip++) {
        float2 c0 = unpack2(acc[ip][0]);
        float2 c1 = unpack2(acc[ip][1]);
        float2 c2 = unpack2(acc[ip][2]);
        float2 c3 = unpack2(acc[ip][3]);
        size_t r0 = (size_t)(b0 + ty * 8 + 2 * ip);
        *(float4*)&out[r0 * ODIM + h * 64 + tx * 4] =
            make_float4(c0.x, c1.x, c2.x, c3.x);
        *(float4*)&out[(r0 + 1) * ODIM + h * 64 + tx * 4] =
            make_float4(c0.y, c1.y, c2.y, c3.y);
    }
}

// ---------------- launcher ----------------
extern "C" void kernel_launch(void* const* d_in, const int* in_sizes, int n_in,
                              void* d_out, int out_size) {
    const int*   vidx = (const int*)d_in[0];    // vox_indices (B,)
    const float* vox  = (const float*)d_in[1];  // voxels (N_VOX,3)
    const float* vf   = (const float*)d_in[2];  // voxel_features (N_VOX,12,256)
    const float* vs   = (const float*)d_in[3];  // voxel_feature_scores (N_VOX,12)
    const int*   cam  = (const int*)d_in[4];    // camera_ids (N_VOX,12)
    const float* ext  = (const float*)d_in[5];  // extrinsics (48,16)
    const float* Wq   = (const float*)d_in[6];  // (24,512)
    const float* Wk   = (const float*)d_in[7];  // (272,512)
    const float* Wv   = (const float*)d_in[8];  // (256,512)
    float* out = (float*)d_out;

    cudaFuncSetAttribute(k_attn2, cudaFuncAttributeMaxDynamicSharedMemorySize, ATTN_SMEM);
    cudaFuncSetAttribute(k_out, cudaFuncAttributeMaxDynamicSharedMemorySize, OUT_SMEM);

    k_init<<<1, 32>>>();
    k_minmax<<<64, 256>>>(vox);
    k_pe<<<B_TOT / 256, 256>>>(vidx, vox);
    k_C2<<<(PE3 * CDIM + 255) / 256, 256>>>(Wq, Wk);
    k_attn2<<<B_TOT / VPB, 256, ATTN_SMEM>>>(vidx, vf, vs, cam, ext);
    k_out<<<dim3(B_TOT / 128, HEADS), 256, OUT_SMEM>>>(Wv, out);
}

// round 4
// speedup vs baseline: 1.8111x; 1.8111x over previous
#include <cuda_runtime.h>
#include <cuda_fp16.h>
#include <math.h>
#include <float.h>

#define B_TOT   16384
#define NVOX    50000
#define MVIEW   12
#define FDIM    256
#define FAUG    272       // FDIM + 16 (extrinsics)
#define HEADS   8
#define QDIM    512       // HEADS*DK
#define ODIM    512       // HEADS*DV
#define PE3     24        // PE_ORDER*3
#define CDIM    2176      // HEADS*FAUG

// ---------------- scratch (static device memory; no allocation) ----------------
__device__ unsigned int g_minb[3];
__device__ unsigned int g_maxb[3];
__device__ float  g_pe[B_TOT * PE3];                      // 1.5 MB
__device__ float  g_C2[PE3 * CDIM];                       // 209 KB
__device__ __half g_qWh[(size_t)B_TOT * CDIM];            // 71 MB
__device__ float  g_mixed[(size_t)B_TOT * HEADS * FDIM];  // 128 MB

// ---------------- packed f32x2 helpers ----------------
__device__ __forceinline__ void ffma2(unsigned long long& d,
                                      unsigned long long a,
                                      unsigned long long b) {
    asm("fma.rn.f32x2 %0, %1, %2, %0;" : "+l"(d) : "l"(a), "l"(b));
}
__device__ __forceinline__ unsigned long long pack2(float x, float y) {
    unsigned long long r;
    asm("mov.b64 %0, {%1, %2};" : "=l"(r) : "f"(x), "f"(y));
    return r;
}
__device__ __forceinline__ float2 unpack2(unsigned long long v) {
    float2 r;
    asm("mov.b64 {%0, %1}, %2;" : "=f"(r.x), "=f"(r.y) : "l"(v));
    return r;
}

// Ordered-uint encoding so unsigned atomicMin/Max implements float min/max.
__device__ __forceinline__ unsigned int fenc(float f) {
    unsigned int u = __float_as_uint(f);
    return (u & 0x80000000u) ? ~u : (u | 0x80000000u);
}
__device__ __forceinline__ float fdec(unsigned int u) {
    u = (u & 0x80000000u) ? (u & 0x7FFFFFFFu) : ~u;
    return __uint_as_float(u);
}

// ---------------- K0: init min/max ----------------
__global__ void k_init() {
    int t = threadIdx.x;
    if (t < 3) { g_minb[t] = 0xFFFFFFFFu; g_maxb[t] = 0u; }
}

// ---------------- K1: per-component min/max over voxels ----------------
__global__ void k_minmax(const float* __restrict__ vox) {
    float mn[3] = {FLT_MAX, FLT_MAX, FLT_MAX};
    float mx[3] = {-FLT_MAX, -FLT_MAX, -FLT_MAX};
    for (int r = blockIdx.x * blockDim.x + threadIdx.x; r < NVOX;
         r += gridDim.x * blockDim.x) {
        #pragma unroll
        for (int c = 0; c < 3; c++) {
            float v = vox[r * 3 + c];
            mn[c] = fminf(mn[c], v);
            mx[c] = fmaxf(mx[c], v);
        }
    }
    #pragma unroll
    for (int c = 0; c < 3; c++) {
        #pragma unroll
        for (int o = 16; o > 0; o >>= 1) {
            mn[c] = fminf(mn[c], __shfl_xor_sync(0xffffffffu, mn[c], o));
            mx[c] = fmaxf(mx[c], __shfl_xor_sync(0xffffffffu, mx[c], o));
        }
    }
    if ((threadIdx.x & 31) == 0) {
        #pragma unroll
        for (int c = 0; c < 3; c++) {
            atomicMin(&g_minb[c], fenc(mn[c]));
            atomicMax(&g_maxb[c], fenc(mx[c]));
        }
    }
}

// ---------------- K2: pe[b, 24] = sinusoidal PE of normalized xyz ----------------
__global__ void __launch_bounds__(256) k_pe(const int* __restrict__ vidx,
                                            const float* __restrict__ vox) {
    int b = blockIdx.x * 256 + threadIdx.x;
    if (b >= B_TOT) return;
    float mn[3], rng[3];
    #pragma unroll
    for (int c = 0; c < 3; c++) {
        float lo = fdec(g_minb[c]);
        float hi = fdec(g_maxb[c]);
        mn[c] = lo; rng[c] = hi - lo;
    }
    int idx = vidx[b];
    float xn[3];
    #pragma unroll
    for (int c = 0; c < 3; c++)
        xn[c] = (vox[idx * 3 + c] - mn[c]) / rng[c] - 0.5f;
    float fr = 1.0f;
    float* dst = g_pe + (size_t)b * PE3;
    #pragma unroll
    for (int p = 0; p < 8; p++) {
        dst[p * 3 + 0] = sinf(xn[0] * fr);
        dst[p * 3 + 1] = sinf(xn[1] * fr);
        dst[p * 3 + 2] = sinf(xn[2] * fr);
        fr *= 2.0f;
    }
}

// ---------------- K3: C2[j, h*272+f] = sum_d Wq[j, h*64+d] * Wk[f, h*64+d] --------
__global__ void __launch_bounds__(256) k_C2(const float* __restrict__ Wq,
                                            const float* __restrict__ Wk) {
    int i = blockIdx.x * 256 + threadIdx.x;
    if (i >= PE3 * CDIM) return;
    int j = i / CDIM;
    int col = i - j * CDIM;
    int h = col / FAUG;
    int f = col - h * FAUG;
    const float4* wq = (const float4*)(Wq + j * QDIM + h * 64);
    const float4* wk = (const float4*)(Wk + (size_t)f * QDIM + h * 64);
    float a0 = 0.f, a1 = 0.f, a2 = 0.f, a3 = 0.f;
    #pragma unroll
    for (int d = 0; d < 16; d++) {
        float4 q = wq[d], k = wk[d];
        a0 += q.x * k.x; a1 += q.y * k.y;
        a2 += q.z * k.z; a3 += q.w * k.w;
    }
    g_C2[i] = (a0 + a1) + (a2 + a3);
}

// ---------------- K4: qW = pe @ C2  (M=16384, N=2176, K=24), fp16 out -------------
// Tiles 128x128, 256 threads, 8x8 register blocking with FFMA2.
__global__ void __launch_bounds__(256) k_qw2() {
    __shared__ float peS[PE3][132];   // [k][row], padded
    __shared__ float c2S[PE3][132];   // [k][col], padded
    int b0 = blockIdx.y * 128;
    int c0 = blockIdx.x * 128;
    int tid = threadIdx.x;

    for (int i = tid; i < 128 * PE3; i += 256) {
        int row = i / PE3;
        int j = i - row * PE3;
        peS[j][row] = g_pe[(size_t)b0 * PE3 + i];
    }
    for (int i = tid; i < PE3 * 128; i += 256) {
        int j = i >> 7, c = i & 127;
        c2S[j][c] = g_C2[j * CDIM + c0 + c];
    }
    __syncthreads();

    int ty = tid >> 4, tx = tid & 15;
    unsigned long long acc[8][4] = {};   // 8 rows x 4 col-pairs
    #pragma unroll
    for (int k = 0; k < PE3; k++) {
        float a[8];
        *(float4*)&a[0] = *(float4*)&peS[k][ty * 8];
        *(float4*)&a[4] = *(float4*)&peS[k][ty * 8 + 4];
        ulonglong2 c01 = *(ulonglong2*)&c2S[k][tx * 8];
        ulonglong2 c23 = *(ulonglong2*)&c2S[k][tx * 8 + 4];
        #pragma unroll
        for (int i = 0; i < 8; i++) {
            unsigned long long a2p = pack2(a[i], a[i]);
            ffma2(acc[i][0], a2p, c01.x);
            ffma2(acc[i][1], a2p, c01.y);
            ffma2(acc[i][2], a2p, c23.x);
            ffma2(acc[i][3], a2p, c23.y);
        }
    }
    #pragma unroll
    for (int i = 0; i < 8; i++) {
        size_t base = (size_t)(b0 + ty * 8 + i) * CDIM + c0 + tx * 8;
        uint4 pk;
        float2 p0 = unpack2(acc[i][0]);
        float2 p1 = unpack2(acc[i][1]);
        float2 p2 = unpack2(acc[i][2]);
        float2 p3 = unpack2(acc[i][3]);
        __half2 h0 = __float22half2_rn(p0);
        __half2 h1 = __float22half2_rn(p1);
        __half2 h2 = __float22half2_rn(p2);
        __half2 h3 = __float22half2_rn(p3);
        pk.x = *(unsigned int*)&h0;
        pk.y = *(unsigned int*)&h1;
        pk.z = *(unsigned int*)&h2;
        pk.w = *(unsigned int*)&h3;
        *(uint4*)&g_qWh[base] = pk;
    }
}

// ---------------- K5: gather + logits + softmax + feature mix ----------------
__global__ void __launch_bounds__(256) k_attn(const int* __restrict__ vidx,
                                              const float* __restrict__ feats_g,
                                              const float* __restrict__ scores_g,
                                              const int* __restrict__ camids,
                                              const float* __restrict__ extr) {
    __shared__ float sf[MVIEW][FDIM];       // 12 KB gathered features
    __shared__ float sqw[CDIM];             // 8.7 KB (fp32, converted on load)
    __shared__ float sext[MVIEW][16];
    __shared__ float sp[HEADS][MVIEW];
    __shared__ float smask[MVIEW];
    __shared__ int   scam[MVIEW];

    int b = blockIdx.x;
    int tid = threadIdx.x;
    int idx = vidx[b];

    const float4* fsrc = (const float4*)(feats_g + (size_t)idx * MVIEW * FDIM);
    float4* fdst = (float4*)&sf[0][0];
    for (int i = tid; i < MVIEW * FDIM / 4; i += 256) fdst[i] = fsrc[i];

    const __half2* qsrc = (const __half2*)(g_qWh + (size_t)b * CDIM);
    for (int i = tid; i < CDIM / 2; i += 256) {
        float2 f = __half22float2(qsrc[i]);
        *(float2*)&sqw[2 * i] = f;
    }

    if (tid < MVIEW) {
        float s = scores_g[(size_t)idx * MVIEW + tid];
        smask[tid] = (s < 0.0f) ? -1e30f : 0.0f;
        scam[tid] = camids[(size_t)idx * MVIEW + tid];
    }
    __syncthreads();
    if (tid < MVIEW * 16) {
        int m = tid >> 4, j = tid & 15;
        sext[m][j] = extr[scam[m] * 16 + j];
    }
    __syncthreads();

    // head w handled by warp w
    int w = tid >> 5, lane = tid & 31;
    float lg[MVIEW];
    #pragma unroll
    for (int m = 0; m < MVIEW; m++) {
        float s = 0.0f;
        #pragma unroll
        for (int u = 0; u < 8; u++) {
            int t = lane + u * 32;
            s += sf[m][t] * sqw[w * FAUG + t];
        }
        if (lane < 16) s += sext[m][lane] * sqw[w * FAUG + 256 + lane];
        #pragma unroll
        for (int o = 16; o > 0; o >>= 1) s += __shfl_xor_sync(0xffffffffu, s, o);
        lg[m] = s * 0.125f + smask[m];   // valid on lane 0
    }
    if (lane == 0) {
        float mx = -FLT_MAX;
        #pragma unroll
        for (int m = 0; m < MVIEW; m++) mx = fmaxf(mx, lg[m]);
        float e[MVIEW], sum = 0.0f;
        #pragma unroll
        for (int m = 0; m < MVIEW; m++) { e[m] = expf(lg[m] - mx); sum += e[m]; }
        float inv = 1.0f / sum;
        #pragma unroll
        for (int m = 0; m < MVIEW; m++) sp[w][m] = e[m] * inv;
    }
    __syncthreads();

    // mixed[b,h,t] = sum_m p[h,m] * feats[m,t]
    float fv[MVIEW];
    #pragma unroll
    for (int m = 0; m < MVIEW; m++) fv[m] = sf[m][tid];
    #pragma unroll
    for (int h = 0; h < HEADS; h++) {
        float acc = 0.0f;
        #pragma unroll
        for (int m = 0; m < MVIEW; m++) acc += sp[h][m] * fv[m];
        g_mixed[(size_t)b * (HEADS * FDIM) + h * FDIM + tid] = acc;
    }
}

// ---------------- K6: out[b, h*64+j] = mixed[b,h,:] @ Wv_h (FFMA2) ----------------
#define OUT_SMEM ((256 * 64 + 32 * 132) * 4)
__global__ void __launch_bounds__(256) k_out(const float* __restrict__ Wv,
                                             float* __restrict__ out) {
    extern __shared__ float sm[];
    float* WvS = sm;                 // [256][64]
    float* As  = sm + 256 * 64;      // [32][132] (k-major, padded)
    int h = blockIdx.y;
    int b0 = blockIdx.x * 128;
    int tid = threadIdx.x;

    for (int i = tid; i < 256 * 16; i += 256) {
        int k = i >> 4, c4 = (i & 15) * 4;
        *(float4*)&WvS[k * 64 + c4] = *(const float4*)&Wv[(size_t)k * ODIM + h * 64 + c4];
    }

    int ty = tid >> 4, tx = tid & 15;
    unsigned long long acc[4][4] = {};   // 4 row-pairs x 4 cols, packed over rows

    for (int k0 = 0; k0 < FDIM; k0 += 32) {
        __syncthreads();
        for (int i = tid; i < 128 * 8; i += 256) {
            int row = i >> 3, k4 = (i & 7) * 4;
            float4 v = *(const float4*)&g_mixed[(size_t)(b0 + row) * (HEADS * FDIM)
                                                + h * FDIM + k0 + k4];
            As[(k4 + 0) * 132 + row] = v.x;
            As[(k4 + 1) * 132 + row] = v.y;
            As[(k4 + 2) * 132 + row] = v.z;
            As[(k4 + 3) * 132 + row] = v.w;
        }
        __syncthreads();
        #pragma unroll
        for (int kk = 0; kk < 32; kk++) {
            ulonglong2 A0 = *(ulonglong2*)&As[kk * 132 + ty * 8];
            ulonglong2 A1 = *(ulonglong2*)&As[kk * 132 + ty * 8 + 4];
            float4 b4 = *(float4*)&WvS[(k0 + kk) * 64 + tx * 4];
            unsigned long long bb0 = pack2(b4.x, b4.x);
            unsigned long long bb1 = pack2(b4.y, b4.y);
            unsigned long long bb2 = pack2(b4.z, b4.z);
            unsigned long long bb3 = pack2(b4.w, b4.w);
            ffma2(acc[0][0], A0.x, bb0); ffma2(acc[0][1], A0.x, bb1);
            ffma2(acc[0][2], A0.x, bb2); ffma2(acc[0][3], A0.x, bb3);
            ffma2(acc[1][0], A0.y, bb0); ffma2(acc[1][1], A0.y, bb1);
            ffma2(acc[1][2], A0.y, bb2); ffma2(acc[1][3], A0.y, bb3);
            ffma2(acc[2][0], A1.x, bb0); ffma2(acc[2][1], A1.x, bb1);
            ffma2(acc[2][2], A1.x, bb2); ffma2(acc[2][3], A1.x, bb3);
            ffma2(acc[3][0], A1.y, bb0); ffma2(acc[3][1], A1.y, bb1);
            ffma2(acc[3][2], A1.y, bb2); ffma2(acc[3][3], A1.y, bb3);
        }
    }
    #pragma unroll
    for (int ip = 0; ip < 4; ip++) {
        float2 c0 = unpack2(acc[ip][0]);
        float2 c1 = unpack2(acc[ip][1]);
        float2 c2 = unpack2(acc[ip][2]);
        float2 c3 = unpack2(acc[ip][3]);
        size_t r0 = (size_t)(b0 + ty * 8 + 2 * ip);
        *(float4*)&out[r0 * ODIM + h * 64 + tx * 4] =
            make_float4(c0.x, c1.x, c2.x, c3.x);
        *(float4*)&out[(r0 + 1) * ODIM + h * 64 + tx * 4] =
            make_float4(c0.y, c1.y, c2.y, c3.y);
    }
}

// ---------------- launcher ----------------
extern "C" void kernel_launch(void* const* d_in, const int* in_sizes, int n_in,
                              void* d_out, int out_size) {
    const int*   vidx = (const int*)d_in[0];    // vox_indices (B,)
    const float* vox  = (const float*)d_in[1];  // voxels (N_VOX,3)
    const float* vf   = (const float*)d_in[2];  // voxel_features (N_VOX,12,256)
    const float* vs   = (const float*)d_in[3];  // voxel_feature_scores (N_VOX,12)
    const int*   cam  = (const int*)d_in[4];    // camera_ids (N_VOX,12)
    const float* ext  = (const float*)d_in[5];  // extrinsics (48,16)
    const float* Wq   = (const float*)d_in[6];  // (24,512)
    const float* Wk   = (const float*)d_in[7];  // (272,512)
    const float* Wv   = (const float*)d_in[8];  // (256,512)
    float* out = (float*)d_out;

    cudaFuncSetAttribute(k_out, cudaFuncAttributeMaxDynamicSharedMemorySize, OUT_SMEM);

    k_init<<<1, 32>>>();
    k_minmax<<<64, 256>>>(vox);
    k_pe<<<B_TOT / 256, 256>>>(vidx, vox);
    k_C2<<<(PE3 * CDIM + 255) / 256, 256>>>(Wq, Wk);
    k_qw2<<<dim3(CDIM / 128, B_TOT / 128), 256>>>();
    k_attn<<<B_TOT, 256>>>(vidx, vf, vs, cam, ext);
    k_out<<<dim3(B_TOT / 128, HEADS), 256, OUT_SMEM>>>(Wv, out);
}

// round 5
// speedup vs baseline: 1.8847x; 1.0406x over previous
#include <cuda_runtime.h>
#include <cuda_fp16.h>
#include <math.h>
#include <float.h>

#define B_TOT   16384
#define NVOX    50000
#define MVIEW   12
#define FDIM    256
#define FAUG    272       // FDIM + 16 (extrinsics)
#define HEADS   8
#define QDIM    512       // HEADS*DK
#define ODIM    512       // HEADS*DV
#define PE3     24        // PE_ORDER*3
#define CDIM    2176      // HEADS*FAUG

// ---------------- scratch (static device memory; no allocation) ----------------
__device__ unsigned int g_minb[3];
__device__ unsigned int g_maxb[3];
__device__ float  g_pe[B_TOT * PE3];                       // 1.5 MB
__device__ float  g_C2[PE3 * CDIM];                        // 209 KB
__device__ __half g_qWh[(size_t)B_TOT * CDIM];             // 71 MB
__device__ __half g_mixedh[(size_t)B_TOT * HEADS * FDIM];  // 67 MB

// ---------------- packed f32x2 helpers ----------------
__device__ __forceinline__ void ffma2(unsigned long long& d,
                                      unsigned long long a,
                                      unsigned long long b) {
    asm("fma.rn.f32x2 %0, %1, %2, %0;" : "+l"(d) : "l"(a), "l"(b));
}
__device__ __forceinline__ unsigned long long pack2(float x, float y) {
    unsigned long long r;
    asm("mov.b64 %0, {%1, %2};" : "=l"(r) : "f"(x), "f"(y));
    return r;
}
__device__ __forceinline__ float2 unpack2(unsigned long long v) {
    float2 r;
    asm("mov.b64 {%0, %1}, %2;" : "=f"(r.x), "=f"(r.y) : "l"(v));
    return r;
}

// Ordered-uint encoding so unsigned atomicMin/Max implements float min/max.
__device__ __forceinline__ unsigned int fenc(float f) {
    unsigned int u = __float_as_uint(f);
    return (u & 0x80000000u) ? ~u : (u | 0x80000000u);
}
__device__ __forceinline__ float fdec(unsigned int u) {
    u = (u & 0x80000000u) ? (u & 0x7FFFFFFFu) : ~u;
    return __uint_as_float(u);
}

// ---------------- K0: init min/max ----------------
__global__ void k_init() {
    int t = threadIdx.x;
    if (t < 3) { g_minb[t] = 0xFFFFFFFFu; g_maxb[t] = 0u; }
}

// ---------------- K1: per-component min/max over voxels ----------------
__global__ void k_minmax(const float* __restrict__ vox) {
    float mn[3] = {FLT_MAX, FLT_MAX, FLT_MAX};
    float mx[3] = {-FLT_MAX, -FLT_MAX, -FLT_MAX};
    for (int r = blockIdx.x * blockDim.x + threadIdx.x; r < NVOX;
         r += gridDim.x * blockDim.x) {
        #pragma unroll
        for (int c = 0; c < 3; c++) {
            float v = vox[r * 3 + c];
            mn[c] = fminf(mn[c], v);
            mx[c] = fmaxf(mx[c], v);
        }
    }
    #pragma unroll
    for (int c = 0; c < 3; c++) {
        #pragma unroll
        for (int o = 16; o > 0; o >>= 1) {
            mn[c] = fminf(mn[c], __shfl_xor_sync(0xffffffffu, mn[c], o));
            mx[c] = fmaxf(mx[c], __shfl_xor_sync(0xffffffffu, mx[c], o));
        }
    }
    if ((threadIdx.x & 31) == 0) {
        #pragma unroll
        for (int c = 0; c < 3; c++) {
            atomicMin(&g_minb[c], fenc(mn[c]));
            atomicMax(&g_maxb[c], fenc(mx[c]));
        }
    }
}

// ---------------- K2: pe[b, 24] = sinusoidal PE of normalized xyz ----------------
__global__ void __launch_bounds__(256) k_pe(const int* __restrict__ vidx,
                                            const float* __restrict__ vox) {
    int b = blockIdx.x * 256 + threadIdx.x;
    if (b >= B_TOT) return;
    float mn[3], rng[3];
    #pragma unroll
    for (int c = 0; c < 3; c++) {
        float lo = fdec(g_minb[c]);
        float hi = fdec(g_maxb[c]);
        mn[c] = lo; rng[c] = hi - lo;
    }
    int idx = vidx[b];
    float xn[3];
    #pragma unroll
    for (int c = 0; c < 3; c++)
        xn[c] = (vox[idx * 3 + c] - mn[c]) / rng[c] - 0.5f;
    float fr = 1.0f;
    float* dst = g_pe + (size_t)b * PE3;
    #pragma unroll
    for (int p = 0; p < 8; p++) {
        dst[p * 3 + 0] = sinf(xn[0] * fr);
        dst[p * 3 + 1] = sinf(xn[1] * fr);
        dst[p * 3 + 2] = sinf(xn[2] * fr);
        fr *= 2.0f;
    }
}

// ---------------- K3: C2[j, h*272+f] = sum_d Wq[j, h*64+d] * Wk[f, h*64+d] --------
__global__ void __launch_bounds__(256) k_C2(const float* __restrict__ Wq,
                                            const float* __restrict__ Wk) {
    int i = blockIdx.x * 256 + threadIdx.x;
    if (i >= PE3 * CDIM) return;
    int j = i / CDIM;
    int col = i - j * CDIM;
    int h = col / FAUG;
    int f = col - h * FAUG;
    const float4* wq = (const float4*)(Wq + j * QDIM + h * 64);
    const float4* wk = (const float4*)(Wk + (size_t)f * QDIM + h * 64);
    float a0 = 0.f, a1 = 0.f, a2 = 0.f, a3 = 0.f;
    #pragma unroll
    for (int d = 0; d < 16; d++) {
        float4 q = wq[d], k = wk[d];
        a0 += q.x * k.x; a1 += q.y * k.y;
        a2 += q.z * k.z; a3 += q.w * k.w;
    }
    g_C2[i] = (a0 + a1) + (a2 + a3);
}

// ---------------- K4: qW = pe @ C2  (M=16384, N=2176, K=24), fp16 out -------------
__global__ void __launch_bounds__(256) k_qw2() {
    __shared__ float peS[PE3][132];   // [k][row], padded
    __shared__ float c2S[PE3][132];   // [k][col], padded
    int b0 = blockIdx.y * 128;
    int c0 = blockIdx.x * 128;
    int tid = threadIdx.x;

    for (int i = tid; i < 128 * PE3; i += 256) {
        int row = i / PE3;
        int j = i - row * PE3;
        peS[j][row] = g_pe[(size_t)b0 * PE3 + i];
    }
    for (int i = tid; i < PE3 * 128; i += 256) {
        int j = i >> 7, c = i & 127;
        c2S[j][c] = g_C2[j * CDIM + c0 + c];
    }
    __syncthreads();

    int ty = tid >> 4, tx = tid & 15;
    unsigned long long acc[8][4] = {};   // 8 rows x 4 col-pairs
    #pragma unroll
    for (int k = 0; k < PE3; k++) {
        float a[8];
        *(float4*)&a[0] = *(float4*)&peS[k][ty * 8];
        *(float4*)&a[4] = *(float4*)&peS[k][ty * 8 + 4];
        ulonglong2 c01 = *(ulonglong2*)&c2S[k][tx * 8];
        ulonglong2 c23 = *(ulonglong2*)&c2S[k][tx * 8 + 4];
        #pragma unroll
        for (int i = 0; i < 8; i++) {
            unsigned long long a2p = pack2(a[i], a[i]);
            ffma2(acc[i][0], a2p, c01.x);
            ffma2(acc[i][1], a2p, c01.y);
            ffma2(acc[i][2], a2p, c23.x);
            ffma2(acc[i][3], a2p, c23.y);
        }
    }
    #pragma unroll
    for (int i = 0; i < 8; i++) {
        size_t base = (size_t)(b0 + ty * 8 + i) * CDIM + c0 + tx * 8;
        uint4 pk;
        __half2 h0 = __float22half2_rn(unpack2(acc[i][0]));
        __half2 h1 = __float22half2_rn(unpack2(acc[i][1]));
        __half2 h2 = __float22half2_rn(unpack2(acc[i][2]));
        __half2 h3 = __float22half2_rn(unpack2(acc[i][3]));
        pk.x = *(unsigned int*)&h0;
        pk.y = *(unsigned int*)&h1;
        pk.z = *(unsigned int*)&h2;
        pk.w = *(unsigned int*)&h3;
        *(uint4*)&g_qWh[base] = pk;
    }
}

// ---------------- K5: gather + logits + softmax + feature mix (fp16 out) ----------
__global__ void __launch_bounds__(256) k_attn(const int* __restrict__ vidx,
                                              const float* __restrict__ feats_g,
                                              const float* __restrict__ scores_g,
                                              const int* __restrict__ camids,
                                              const float* __restrict__ extr) {
    __shared__ float sf[MVIEW][FDIM];       // 12 KB gathered features
    __shared__ float sqw[CDIM];             // 8.7 KB (fp32, converted on load)
    __shared__ float sext[MVIEW][16];
    __shared__ float sp[HEADS][MVIEW];
    __shared__ float smask[MVIEW];
    __shared__ int   scam[MVIEW];

    int b = blockIdx.x;
    int tid = threadIdx.x;
    int idx = vidx[b];

    const float4* fsrc = (const float4*)(feats_g + (size_t)idx * MVIEW * FDIM);
    float4* fdst = (float4*)&sf[0][0];
    for (int i = tid; i < MVIEW * FDIM / 4; i += 256) fdst[i] = fsrc[i];

    const __half2* qsrc = (const __half2*)(g_qWh + (size_t)b * CDIM);
    for (int i = tid; i < CDIM / 2; i += 256) {
        float2 f = __half22float2(qsrc[i]);
        *(float2*)&sqw[2 * i] = f;
    }

    if (tid < MVIEW) {
        float s = scores_g[(size_t)idx * MVIEW + tid];
        smask[tid] = (s < 0.0f) ? -1e30f : 0.0f;
        scam[tid] = camids[(size_t)idx * MVIEW + tid];
    }
    __syncthreads();
    if (tid < MVIEW * 16) {
        int m = tid >> 4, j = tid & 15;
        sext[m][j] = extr[scam[m] * 16 + j];
    }
    __syncthreads();

    // head w handled by warp w
    int w = tid >> 5, lane = tid & 31;
    float lg[MVIEW];
    #pragma unroll
    for (int m = 0; m < MVIEW; m++) {
        float s = 0.0f;
        #pragma unroll
        for (int u = 0; u < 8; u++) {
            int t = lane + u * 32;
            s += sf[m][t] * sqw[w * FAUG + t];
        }
        if (lane < 16) s += sext[m][lane] * sqw[w * FAUG + 256 + lane];
        #pragma unroll
        for (int o = 16; o > 0; o >>= 1) s += __shfl_xor_sync(0xffffffffu, s, o);
        lg[m] = s * 0.125f + smask[m];   // valid on lane 0
    }
    if (lane == 0) {
        float mx = -FLT_MAX;
        #pragma unroll
        for (int m = 0; m < MVIEW; m++) mx = fmaxf(mx, lg[m]);
        float e[MVIEW], sum = 0.0f;
        #pragma unroll
        for (int m = 0; m < MVIEW; m++) { e[m] = expf(lg[m] - mx); sum += e[m]; }
        float inv = 1.0f / sum;
        #pragma unroll
        for (int m = 0; m < MVIEW; m++) sp[w][m] = e[m] * inv;
    }
    __syncthreads();

    // mixed[b,h,t] = sum_m p[h,m]*feats[m,t]; thread owns 2 adjacent t, 4 heads.
    int part = tid >> 7;            // 0..1
    int t2 = (tid & 127) * 2;       // even column
    float2 fv2[MVIEW];
    #pragma unroll
    for (int m = 0; m < MVIEW; m++) fv2[m] = *(float2*)&sf[m][t2];
    #pragma unroll
    for (int hh = 0; hh < 4; hh++) {
        int h = hh * 2 + part;
        float a0 = 0.0f, a1 = 0.0f;
        #pragma unroll
        for (int m = 0; m < MVIEW; m++) {
            float p = sp[h][m];
            a0 += p * fv2[m].x;
            a1 += p * fv2[m].y;
        }
        *(__half2*)&g_mixedh[((size_t)b * HEADS + h) * FDIM + t2] =
            __floats2half2_rn(a0, a1);
    }
}

// ---------------- K6: out[b, h*64+j] = mixed[b,h,:] @ Wv_h (FFMA2) ----------------
#define OUT_SMEM ((256 * 64 + 32 * 132) * 4)
__global__ void __launch_bounds__(256) k_out(const float* __restrict__ Wv,
                                             float* __restrict__ out) {
    extern __shared__ float sm[];
    float* WvS = sm;                 // [256][64]
    float* As  = sm + 256 * 64;      // [32][132] (k-major, padded)
    int h = blockIdx.y;
    int b0 = blockIdx.x * 128;
    int tid = threadIdx.x;

    for (int i = tid; i < 256 * 16; i += 256) {
        int k = i >> 4, c4 = (i & 15) * 4;
        *(float4*)&WvS[k * 64 + c4] = *(const float4*)&Wv[(size_t)k * ODIM + h * 64 + c4];
    }

    int ty = tid >> 4, tx = tid & 15;
    unsigned long long acc[4][4] = {};   // 4 row-pairs x 4 cols, packed over rows

    for (int k0 = 0; k0 < FDIM; k0 += 32) {
        __syncthreads();
        // load A slab (half) transposed: As[k][row]
        for (int i = tid; i < 128 * 8; i += 256) {
            int row = i >> 3, k4 = (i & 7) * 4;
            uint2 raw = *(const uint2*)&g_mixedh[((size_t)(b0 + row) * HEADS + h) * FDIM
                                                 + k0 + k4];
            float2 v01 = __half22float2(*(__half2*)&raw.x);
            float2 v23 = __half22float2(*(__half2*)&raw.y);
            As[(k4 + 0) * 132 + row] = v01.x;
            As[(k4 + 1) * 132 + row] = v01.y;
            As[(k4 + 2) * 132 + row] = v23.x;
            As[(k4 + 3) * 132 + row] = v23.y;
        }
        __syncthreads();
        #pragma unroll
        for (int kk = 0; kk < 32; kk++) {
            ulonglong2 A0 = *(ulonglong2*)&As[kk * 132 + ty * 8];
            ulonglong2 A1 = *(ulonglong2*)&As[kk * 132 + ty * 8 + 4];
            float4 b4 = *(float4*)&WvS[(k0 + kk) * 64 + tx * 4];
            unsigned long long bb0 = pack2(b4.x, b4.x);
            unsigned long long bb1 = pack2(b4.y, b4.y);
            unsigned long long bb2 = pack2(b4.z, b4.z);
            unsigned long long bb3 = pack2(b4.w, b4.w);
            ffma2(acc[0][0], A0.x, bb0); ffma2(acc[0][1], A0.x, bb1);
            ffma2(acc[0][2], A0.x, bb2); ffma2(acc[0][3], A0.x, bb3);
            ffma2(acc[1][0], A0.y, bb0); ffma2(acc[1][1], A0.y, bb1);
            ffma2(acc[1][2], A0.y, bb2); ffma2(acc[1][3], A0.y, bb3);
            ffma2(acc[2][0], A1.x, bb0); ffma2(acc[2][1], A1.x, bb1);
            ffma2(acc[2][2], A1.x, bb2); ffma2(acc[2][3], A1.x, bb3);
            ffma2(acc[3][0], A1.y, bb0); ffma2(acc[3][1], A1.y, bb1);
            ffma2(acc[3][2], A1.y, bb2); ffma2(acc[3][3], A1.y, bb3);
        }
    }
    #pragma unroll
    for (int ip = 0; ip < 4; ip++) {
        float2 c0 = unpack2(acc[ip][0]);
        float2 c1 = unpack2(acc[ip][1]);
        float2 c2 = unpack2(acc[ip][2]);
        float2 c3 = unpack2(acc[ip][3]);
        size_t r0 = (size_t)(b0 + ty * 8 + 2 * ip);
        *(float4*)&out[r0 * ODIM + h * 64 + tx * 4] =
            make_float4(c0.x, c1.x, c2.x, c3.x);
        *(float4*)&out[(r0 + 1) * ODIM + h * 64 + tx * 4] =
            make_float4(c0.y, c1.y, c2.y, c3.y);
    }
}

// ---------------- launcher ----------------
extern "C" void kernel_launch(void* const* d_in, const int* in_sizes, int n_in,
                              void* d_out, int out_size) {
    const int*   vidx = (const int*)d_in[0];    // vox_indices (B,)
    const float* vox  = (const float*)d_in[1];  // voxels (N_VOX,3)
    const float* vf   = (const float*)d_in[2];  // voxel_features (N_VOX,12,256)
    const float* vs   = (const float*)d_in[3];  // voxel_feature_scores (N_VOX,12)
    const int*   cam  = (const int*)d_in[4];    // camera_ids (N_VOX,12)
    const float* ext  = (const float*)d_in[5];  // extrinsics (48,16)
    const float* Wq   = (const float*)d_in[6];  // (24,512)
    const float* Wk   = (const float*)d_in[7];  // (272,512)
    const float* Wv   = (const float*)d_in[8];  // (256,512)
    float* out = (float*)d_out;

    cudaFuncSetAttribute(k_out, cudaFuncAttributeMaxDynamicSharedMemorySize, OUT_SMEM);

    k_init<<<1, 32>>>();
    k_minmax<<<64, 256>>>(vox);
    k_pe<<<B_TOT / 256, 256>>>(vidx, vox);
    k_C2<<<(PE3 * CDIM + 255) / 256, 256>>>(Wq, Wk);
    k_qw2<<<dim3(CDIM / 128, B_TOT / 128), 256>>>();
    k_attn<<<B_TOT, 256>>>(vidx, vf, vs, cam, ext);
    k_out<<<dim3(B_TOT / 128, HEADS), 256, OUT_SMEM>>>(Wv, out);
}

// round 6
// speedup vs baseline: 2.4033x; 1.2752x over previous
#include <cuda_runtime.h>
#include <cuda_fp16.h>
#include <math.h>
#include <float.h>

#define B_TOT   16384
#define NVOX    50000
#define MVIEW   12
#define FDIM    256
#define FAUG    272       // FDIM + 16 (extrinsics)
#define HEADS   8
#define QDIM    512       // HEADS*DK
#define ODIM    512       // HEADS*DV
#define PE3     24        // PE_ORDER*3
#define CDIM    2176      // HEADS*FAUG

// ---------------- scratch (static device memory; no allocation) ----------------
__device__ unsigned int g_minb[3];
__device__ unsigned int g_maxb[3];
__device__ float  g_pe[B_TOT * PE3];                       // 1.5 MB
__device__ float  g_C2[PE3 * CDIM];                        // 209 KB
__device__ __half g_qWh[(size_t)B_TOT * CDIM];             // 71 MB
__device__ __half g_mixedh[(size_t)B_TOT * HEADS * FDIM];  // 67 MB
__device__ __half g_Wvt[ODIM * FDIM];                      // 512 KB  [h*64+n][k]

// ---------------- packed f32x2 helpers ----------------
__device__ __forceinline__ void ffma2(unsigned long long& d,
                                      unsigned long long a,
                                      unsigned long long b) {
    asm("fma.rn.f32x2 %0, %1, %2, %0;" : "+l"(d) : "l"(a), "l"(b));
}
__device__ __forceinline__ unsigned long long pack2(float x, float y) {
    unsigned long long r;
    asm("mov.b64 %0, {%1, %2};" : "=l"(r) : "f"(x), "f"(y));
    return r;
}
__device__ __forceinline__ float2 unpack2(unsigned long long v) {
    float2 r;
    asm("mov.b64 {%0, %1}, %2;" : "=f"(r.x), "=f"(r.y) : "l"(v));
    return r;
}
__device__ __forceinline__ unsigned su32(const void* p) {
    return (unsigned)__cvta_generic_to_shared(p);
}

// Ordered-uint encoding so unsigned atomicMin/Max implements float min/max.
__device__ __forceinline__ unsigned int fenc(float f) {
    unsigned int u = __float_as_uint(f);
    return (u & 0x80000000u) ? ~u : (u | 0x80000000u);
}
__device__ __forceinline__ float fdec(unsigned int u) {
    u = (u & 0x80000000u) ? (u & 0x7FFFFFFFu) : ~u;
    return __uint_as_float(u);
}

// ---------------- K0: init min/max ----------------
__global__ void k_init() {
    int t = threadIdx.x;
    if (t < 3) { g_minb[t] = 0xFFFFFFFFu; g_maxb[t] = 0u; }
}

// ---------------- K1: per-component min/max over voxels ----------------
__global__ void k_minmax(const float* __restrict__ vox) {
    float mn[3] = {FLT_MAX, FLT_MAX, FLT_MAX};
    float mx[3] = {-FLT_MAX, -FLT_MAX, -FLT_MAX};
    for (int r = blockIdx.x * blockDim.x + threadIdx.x; r < NVOX;
         r += gridDim.x * blockDim.x) {
        #pragma unroll
        for (int c = 0; c < 3; c++) {
            float v = vox[r * 3 + c];
            mn[c] = fminf(mn[c], v);
            mx[c] = fmaxf(mx[c], v);
        }
    }
    #pragma unroll
    for (int c = 0; c < 3; c++) {
        #pragma unroll
        for (int o = 16; o > 0; o >>= 1) {
            mn[c] = fminf(mn[c], __shfl_xor_sync(0xffffffffu, mn[c], o));
            mx[c] = fmaxf(mx[c], __shfl_xor_sync(0xffffffffu, mx[c], o));
        }
    }
    if ((threadIdx.x & 31) == 0) {
        #pragma unroll
        for (int c = 0; c < 3; c++) {
            atomicMin(&g_minb[c], fenc(mn[c]));
            atomicMax(&g_maxb[c], fenc(mx[c]));
        }
    }
}

// ---------------- K2: pe[b, 24] = sinusoidal PE of normalized xyz ----------------
__global__ void __launch_bounds__(256) k_pe(const int* __restrict__ vidx,
                                            const float* __restrict__ vox) {
    int b = blockIdx.x * 256 + threadIdx.x;
    if (b >= B_TOT) return;
    float mn[3], rng[3];
    #pragma unroll
    for (int c = 0; c < 3; c++) {
        float lo = fdec(g_minb[c]);
        float hi = fdec(g_maxb[c]);
        mn[c] = lo; rng[c] = hi - lo;
    }
    int idx = vidx[b];
    float xn[3];
    #pragma unroll
    for (int c = 0; c < 3; c++)
        xn[c] = (vox[idx * 3 + c] - mn[c]) / rng[c] - 0.5f;
    float fr = 1.0f;
    float* dst = g_pe + (size_t)b * PE3;
    #pragma unroll
    for (int p = 0; p < 8; p++) {
        dst[p * 3 + 0] = sinf(xn[0] * fr);
        dst[p * 3 + 1] = sinf(xn[1] * fr);
        dst[p * 3 + 2] = sinf(xn[2] * fr);
        fr *= 2.0f;
    }
}

// ---------------- K3: C2[j, h*272+f] = sum_d Wq[j, h*64+d] * Wk[f, h*64+d] --------
__global__ void __launch_bounds__(128) k_C2(const float* __restrict__ Wq,
                                            const float* __restrict__ Wk) {
    int i = blockIdx.x * 128 + threadIdx.x;
    if (i >= PE3 * CDIM) return;
    int j = i / CDIM;
    int col = i - j * CDIM;
    int h = col / FAUG;
    int f = col - h * FAUG;
    const float4* wq = (const float4*)(Wq + j * QDIM + h * 64);
    const float4* wk = (const float4*)(Wk + (size_t)f * QDIM + h * 64);
    float a0 = 0.f, a1 = 0.f, a2 = 0.f, a3 = 0.f;
    #pragma unroll
    for (int d = 0; d < 16; d++) {
        float4 q = wq[d], k = wk[d];
        a0 += q.x * k.x; a1 += q.y * k.y;
        a2 += q.z * k.z; a3 += q.w * k.w;
    }
    g_C2[i] = (a0 + a1) + (a2 + a3);
}

// ---------------- K3b: Wvt[h*64+n][k] = (half)Wv[k][h*64+n] ----------------
__global__ void __launch_bounds__(256) k_wvt(const float* __restrict__ Wv) {
    int i = blockIdx.x * 256 + threadIdx.x;
    if (i >= ODIM * FDIM) return;
    int r = i >> 8, k = i & 255;
    g_Wvt[i] = __float2half(Wv[(size_t)k * ODIM + r]);
}

// ---------------- K4: qW = pe @ C2  (M=16384, N=2176, K=24), fp16 out -------------
__global__ void __launch_bounds__(256) k_qw2() {
    __shared__ float peS[PE3][132];   // [k][row], padded
    __shared__ float c2S[PE3][132];   // [k][col], padded
    int b0 = blockIdx.y * 128;
    int c0 = blockIdx.x * 128;
    int tid = threadIdx.x;

    for (int i = tid; i < 128 * PE3; i += 256) {
        int row = i / PE3;
        int j = i - row * PE3;
        peS[j][row] = g_pe[(size_t)b0 * PE3 + i];
    }
    for (int i = tid; i < PE3 * 128; i += 256) {
        int j = i >> 7, c = i & 127;
        c2S[j][c] = g_C2[j * CDIM + c0 + c];
    }
    __syncthreads();

    int ty = tid >> 4, tx = tid & 15;
    unsigned long long acc[8][4] = {};   // 8 rows x 4 col-pairs
    #pragma unroll
    for (int k = 0; k < PE3; k++) {
        float a[8];
        *(float4*)&a[0] = *(float4*)&peS[k][ty * 8];
        *(float4*)&a[4] = *(float4*)&peS[k][ty * 8 + 4];
        ulonglong2 c01 = *(ulonglong2*)&c2S[k][tx * 8];
        ulonglong2 c23 = *(ulonglong2*)&c2S[k][tx * 8 + 4];
        #pragma unroll
        for (int i = 0; i < 8; i++) {
            unsigned long long a2p = pack2(a[i], a[i]);
            ffma2(acc[i][0], a2p, c01.x);
            ffma2(acc[i][1], a2p, c01.y);
            ffma2(acc[i][2], a2p, c23.x);
            ffma2(acc[i][3], a2p, c23.y);
        }
    }
    #pragma unroll
    for (int i = 0; i < 8; i++) {
        size_t base = (size_t)(b0 + ty * 8 + i) * CDIM + c0 + tx * 8;
        uint4 pk;
        __half2 h0 = __float22half2_rn(unpack2(acc[i][0]));
        __half2 h1 = __float22half2_rn(unpack2(acc[i][1]));
        __half2 h2 = __float22half2_rn(unpack2(acc[i][2]));
        __half2 h3 = __float22half2_rn(unpack2(acc[i][3]));
        pk.x = *(unsigned int*)&h0;
        pk.y = *(unsigned int*)&h1;
        pk.z = *(unsigned int*)&h2;
        pk.w = *(unsigned int*)&h3;
        *(uint4*)&g_qWh[base] = pk;
    }
}

// ---------------- K5: gather + logits + softmax + feature mix (fp16 out) ----------
__global__ void __launch_bounds__(256) k_attn(const int* __restrict__ vidx,
                                              const float* __restrict__ feats_g,
                                              const float* __restrict__ scores_g,
                                              const int* __restrict__ camids,
                                              const float* __restrict__ extr) {
    __shared__ float sf[MVIEW][FDIM];       // 12 KB gathered features
    __shared__ float sqw[CDIM];             // 8.7 KB (fp32, converted on load)
    __shared__ float sext[MVIEW][16];
    __shared__ float sp[HEADS][MVIEW];
    __shared__ float smask[MVIEW];
    __shared__ int   scam[MVIEW];

    int b = blockIdx.x;
    int tid = threadIdx.x;
    int idx = vidx[b];

    const float4* fsrc = (const float4*)(feats_g + (size_t)idx * MVIEW * FDIM);
    float4* fdst = (float4*)&sf[0][0];
    for (int i = tid; i < MVIEW * FDIM / 4; i += 256) fdst[i] = fsrc[i];

    const __half2* qsrc = (const __half2*)(g_qWh + (size_t)b * CDIM);
    for (int i = tid; i < CDIM / 2; i += 256) {
        float2 f = __half22float2(qsrc[i]);
        *(float2*)&sqw[2 * i] = f;
    }

    if (tid < MVIEW) {
        float s = scores_g[(size_t)idx * MVIEW + tid];
        smask[tid] = (s < 0.0f) ? -1e30f : 0.0f;
        scam[tid] = camids[(size_t)idx * MVIEW + tid];
    }
    __syncthreads();
    if (tid < MVIEW * 16) {
        int m = tid >> 4, j = tid & 15;
        sext[m][j] = extr[scam[m] * 16 + j];
    }
    __syncthreads();

    // head w handled by warp w
    int w = tid >> 5, lane = tid & 31;
    float lg[MVIEW];
    #pragma unroll
    for (int m = 0; m < MVIEW; m++) {
        float s = 0.0f;
        #pragma unroll
        for (int u = 0; u < 8; u++) {
            int t = lane + u * 32;
            s += sf[m][t] * sqw[w * FAUG + t];
        }
        if (lane < 16) s += sext[m][lane] * sqw[w * FAUG + 256 + lane];
        #pragma unroll
        for (int o = 16; o > 0; o >>= 1) s += __shfl_xor_sync(0xffffffffu, s, o);
        lg[m] = s * 0.125f + smask[m];   // valid on lane 0
    }
    if (lane == 0) {
        float mx = -FLT_MAX;
        #pragma unroll
        for (int m = 0; m < MVIEW; m++) mx = fmaxf(mx, lg[m]);
        float e[MVIEW], sum = 0.0f;
        #pragma unroll
        for (int m = 0; m < MVIEW; m++) { e[m] = __expf(lg[m] - mx); sum += e[m]; }
        float inv = 1.0f / sum;
        #pragma unroll
        for (int m = 0; m < MVIEW; m++) sp[w][m] = e[m] * inv;
    }
    __syncthreads();

    // mixed[b,h,t] = sum_m p[h,m]*feats[m,t]; thread owns 2 adjacent t, 4 heads.
    int part = tid >> 7;            // 0..1
    int t2 = (tid & 127) * 2;       // even column
    float2 fv2[MVIEW];
    #pragma unroll
    for (int m = 0; m < MVIEW; m++) fv2[m] = *(float2*)&sf[m][t2];
    #pragma unroll
    for (int hh = 0; hh < 4; hh++) {
        int h = hh * 2 + part;
        float a0 = 0.0f, a1 = 0.0f;
        #pragma unroll
        for (int m = 0; m < MVIEW; m++) {
            float p = sp[h][m];
            a0 += p * fv2[m].x;
            a1 += p * fv2[m].y;
        }
        *(__half2*)&g_mixedh[((size_t)b * HEADS + h) * FDIM + t2] =
            __floats2half2_rn(a0, a1);
    }
}

// ---------------- K6: out = mixedh @ Wvt (HMMA m16n8k16) ----------------
#define LDA 264   // 256 + 8 halfs padding (16B), keeps 16B alignment per row
#define OUT_SMEM_H ((128 * LDA + 64 * LDA) * 2)
__global__ void __launch_bounds__(256) k_out_hmma(float* __restrict__ out) {
    extern __shared__ __half smh[];
    __half* Ah = smh;               // [128][LDA]  mixed rows
    __half* Bt = smh + 128 * LDA;   // [64][LDA]   Wv_h transposed (n-major, k inner)
    int h = blockIdx.y;
    int b0 = blockIdx.x * 128;
    int tid = threadIdx.x;

    for (int i = tid; i < 128 * 32; i += 256) {
        int r = i >> 5, c8 = (i & 31) * 8;
        *(uint4*)&Ah[r * LDA + c8] =
            *(const uint4*)&g_mixedh[((size_t)(b0 + r) * HEADS + h) * FDIM + c8];
    }
    for (int i = tid; i < 64 * 32; i += 256) {
        int r = i >> 5, c8 = (i & 31) * 8;
        *(uint4*)&Bt[r * LDA + c8] =
            *(const uint4*)&g_Wvt[(size_t)(h * 64 + r) * FDIM + c8];
    }
    __syncthreads();

    int w = tid >> 5, lane = tid & 31;
    int m0 = w * 16;
    float acc[8][4] = {};

    unsigned aBase = su32(Ah + (m0 + (lane & 15)) * LDA + (lane >> 4) * 8);
    unsigned bBase = su32(Bt + (lane & 7) * LDA + ((lane >> 3) & 1) * 8);

    #pragma unroll
    for (int ks = 0; ks < 16; ks++) {
        unsigned a0, a1, a2, a3;
        asm volatile(
            "ldmatrix.sync.aligned.m8n8.x4.shared.b16 {%0,%1,%2,%3}, [%4];"
            : "=r"(a0), "=r"(a1), "=r"(a2), "=r"(a3)
            : "r"(aBase + ks * 32));
        #pragma unroll
        for (int nf = 0; nf < 8; nf++) {
            unsigned br0, br1;
            asm volatile(
                "ldmatrix.sync.aligned.m8n8.x2.shared.b16 {%0,%1}, [%2];"
                : "=r"(br0), "=r"(br1)
                : "r"(bBase + (unsigned)(nf * 8 * LDA * 2) + ks * 32));
            asm volatile(
                "mma.sync.aligned.m16n8k16.row.col.f32.f16.f16.f32 "
                "{%0,%1,%2,%3},{%4,%5,%6,%7},{%8,%9},{%0,%1,%2,%3};"
                : "+f"(acc[nf][0]), "+f"(acc[nf][1]),
                  "+f"(acc[nf][2]), "+f"(acc[nf][3])
                : "r"(a0), "r"(a1), "r"(a2), "r"(a3), "r"(br0), "r"(br1));
        }
    }

    int g = lane >> 2, tg = lane & 3;
    #pragma unroll
    for (int nf = 0; nf < 8; nf++) {
        size_t r = (size_t)(b0 + m0 + g);
        int col = h * 64 + nf * 8 + 2 * tg;
        *(float2*)&out[r * ODIM + col]       = make_float2(acc[nf][0], acc[nf][1]);
        *(float2*)&out[(r + 8) * ODIM + col] = make_float2(acc[nf][2], acc[nf][3]);
    }
}

// ---------------- launcher ----------------
extern "C" void kernel_launch(void* const* d_in, const int* in_sizes, int n_in,
                              void* d_out, int out_size) {
    const int*   vidx = (const int*)d_in[0];    // vox_indices (B,)
    const float* vox  = (const float*)d_in[1];  // voxels (N_VOX,3)
    const float* vf   = (const float*)d_in[2];  // voxel_features (N_VOX,12,256)
    const float* vs   = (const float*)d_in[3];  // voxel_feature_scores (N_VOX,12)
    const int*   cam  = (const int*)d_in[4];    // camera_ids (N_VOX,12)
    const float* ext  = (const float*)d_in[5];  // extrinsics (48,16)
    const float* Wq   = (const float*)d_in[6];  // (24,512)
    const float* Wk   = (const float*)d_in[7];  // (272,512)
    const float* Wv   = (const float*)d_in[8];  // (256,512)
    float* out = (float*)d_out;

    cudaFuncSetAttribute(k_out_hmma, cudaFuncAttributeMaxDynamicSharedMemorySize,
                         OUT_SMEM_H);

    k_init<<<1, 32>>>();
    k_minmax<<<64, 256>>>(vox);
    k_pe<<<B_TOT / 256, 256>>>(vidx, vox);
    k_C2<<<(PE3 * CDIM + 127) / 128, 128>>>(Wq, Wk);
    k_wvt<<<(ODIM * FDIM + 255) / 256, 256>>>(Wv);
    k_qw2<<<dim3(CDIM / 128, B_TOT / 128), 256>>>();
    k_attn<<<B_TOT, 256>>>(vidx, vf, vs, cam, ext);
    k_out_hmma<<<dim3(B_TOT / 128, HEADS), 256, OUT_SMEM_H>>>(out);
}

// round 7
// speedup vs baseline: 2.4307x; 1.0114x over previous
#include <cuda_runtime.h>
#include <cuda_fp16.h>
#include <math.h>
#include <float.h>

#define B_TOT   16384
#define NVOX    50000
#define MVIEW   12
#define FDIM    256
#define FAUG    272       // FDIM + 16 (extrinsics)
#define HEADS   8
#define QDIM    512       // HEADS*DK
#define ODIM    512       // HEADS*DV
#define PE3     24        // PE_ORDER*3
#define CDIM    2176      // HEADS*FAUG

// ---------------- scratch (static device memory; no allocation) ----------------
__device__ float  g_mn[3];
__device__ float  g_rinv[3];
__device__ float  g_C2[PE3 * CDIM];                        // 209 KB
__device__ __half g_qWh[(size_t)B_TOT * CDIM];             // 71 MB
__device__ __half g_mixedh[(size_t)B_TOT * HEADS * FDIM];  // 67 MB
__device__ __half g_Wvt[ODIM * FDIM];                      // 512 KB  [h*64+n][k]

// ---------------- packed f32x2 helpers ----------------
__device__ __forceinline__ void ffma2(unsigned long long& d,
                                      unsigned long long a,
                                      unsigned long long b) {
    asm("fma.rn.f32x2 %0, %1, %2, %0;" : "+l"(d) : "l"(a), "l"(b));
}
__device__ __forceinline__ unsigned long long pack2(float x, float y) {
    unsigned long long r;
    asm("mov.b64 %0, {%1, %2};" : "=l"(r) : "f"(x), "f"(y));
    return r;
}
__device__ __forceinline__ float2 unpack2(unsigned long long v) {
    float2 r;
    asm("mov.b64 {%0, %1}, %2;" : "=f"(r.x), "=f"(r.y) : "l"(v));
    return r;
}
__device__ __forceinline__ unsigned su32(const void* p) {
    return (unsigned)__cvta_generic_to_shared(p);
}

// ---------------- K0: fused C2 + Wv transpose prep ----------------
// C2[j, h*272+f] = sum_d Wq[j, h*64+d] * Wk[f, h*64+d]   (52224 elems)
// Wvt[h*64+n][k] = (half)Wv[k][h*64+n]                    (131072 elems)
__global__ void __launch_bounds__(256) k_prep(const float* __restrict__ Wq,
                                              const float* __restrict__ Wk,
                                              const float* __restrict__ Wv) {
    int i = blockIdx.x * 256 + threadIdx.x;
    if (i < PE3 * CDIM) {
        int j = i / CDIM;
        int col = i - j * CDIM;
        int h = col / FAUG;
        int f = col - h * FAUG;
        const float4* wq = (const float4*)(Wq + j * QDIM + h * 64);
        const float4* wk = (const float4*)(Wk + (size_t)f * QDIM + h * 64);
        float a0 = 0.f, a1 = 0.f, a2 = 0.f, a3 = 0.f;
        #pragma unroll
        for (int d = 0; d < 16; d++) {
            float4 q = wq[d], k = wk[d];
            a0 += q.x * k.x; a1 += q.y * k.y;
            a2 += q.z * k.z; a3 += q.w * k.w;
        }
        g_C2[i] = (a0 + a1) + (a2 + a3);
    } else {
        int t = i - PE3 * CDIM;
        if (t < ODIM * FDIM) {
            int r = t >> 8, k = t & 255;
            g_Wvt[t] = __float2half(Wv[(size_t)k * ODIM + r]);
        }
    }
}

// ---------------- K1: single-block min/max (no atomics, no init) ----------------
__global__ void __launch_bounds__(1024) k_minmax(const float* __restrict__ vox) {
    __shared__ float red[32][6];
    int tid = threadIdx.x;
    float mn[3] = {FLT_MAX, FLT_MAX, FLT_MAX};
    float mx[3] = {-FLT_MAX, -FLT_MAX, -FLT_MAX};
    for (int r = tid; r < NVOX; r += 1024) {
        #pragma unroll
        for (int c = 0; c < 3; c++) {
            float v = vox[r * 3 + c];
            mn[c] = fminf(mn[c], v);
            mx[c] = fmaxf(mx[c], v);
        }
    }
    #pragma unroll
    for (int c = 0; c < 3; c++) {
        #pragma unroll
        for (int o = 16; o > 0; o >>= 1) {
            mn[c] = fminf(mn[c], __shfl_xor_sync(0xffffffffu, mn[c], o));
            mx[c] = fmaxf(mx[c], __shfl_xor_sync(0xffffffffu, mx[c], o));
        }
    }
    if ((tid & 31) == 0) {
        #pragma unroll
        for (int c = 0; c < 3; c++) {
            red[tid >> 5][c]     = mn[c];
            red[tid >> 5][3 + c] = mx[c];
        }
    }
    __syncthreads();
    if (tid < 32) {
        #pragma unroll
        for (int c = 0; c < 3; c++) { mn[c] = red[tid][c]; mx[c] = red[tid][3 + c]; }
        #pragma unroll
        for (int c = 0; c < 3; c++) {
            #pragma unroll
            for (int o = 16; o > 0; o >>= 1) {
                mn[c] = fminf(mn[c], __shfl_xor_sync(0xffffffffu, mn[c], o));
                mx[c] = fmaxf(mx[c], __shfl_xor_sync(0xffffffffu, mx[c], o));
            }
        }
        if (tid < 3) {
            g_mn[tid] = mn[tid];
            g_rinv[tid] = 1.0f / (mx[tid] - mn[tid]);
        }
    }
}

// ---------------- K2: qW = PE(xyz) @ C2  (pe computed in-kernel) ----------------
__global__ void __launch_bounds__(256) k_qw2(const int* __restrict__ vidx,
                                             const float* __restrict__ vox) {
    __shared__ float peS[PE3][132];   // [k][row], padded
    __shared__ float c2S[PE3][132];   // [k][col], padded
    int b0 = blockIdx.y * 128;
    int c0 = blockIdx.x * 128;
    int tid = threadIdx.x;

    if (tid < 128) {
        int idx = vidx[b0 + tid];
        float xn[3];
        #pragma unroll
        for (int c = 0; c < 3; c++)
            xn[c] = (vox[idx * 3 + c] - g_mn[c]) * g_rinv[c] - 0.5f;
        float fr = 1.0f;
        #pragma unroll
        for (int p = 0; p < 8; p++) {
            peS[p * 3 + 0][tid] = sinf(xn[0] * fr);
            peS[p * 3 + 1][tid] = sinf(xn[1] * fr);
            peS[p * 3 + 2][tid] = sinf(xn[2] * fr);
            fr *= 2.0f;
        }
    }
    for (int i = tid; i < PE3 * 128; i += 256) {
        int j = i >> 7, c = i & 127;
        c2S[j][c] = g_C2[j * CDIM + c0 + c];
    }
    __syncthreads();

    int ty = tid >> 4, tx = tid & 15;
    unsigned long long acc[8][4] = {};   // 8 rows x 4 col-pairs
    #pragma unroll
    for (int k = 0; k < PE3; k++) {
        float a[8];
        *(float4*)&a[0] = *(float4*)&peS[k][ty * 8];
        *(float4*)&a[4] = *(float4*)&peS[k][ty * 8 + 4];
        ulonglong2 c01 = *(ulonglong2*)&c2S[k][tx * 8];
        ulonglong2 c23 = *(ulonglong2*)&c2S[k][tx * 8 + 4];
        #pragma unroll
        for (int i = 0; i < 8; i++) {
            unsigned long long a2p = pack2(a[i], a[i]);
            ffma2(acc[i][0], a2p, c01.x);
            ffma2(acc[i][1], a2p, c01.y);
            ffma2(acc[i][2], a2p, c23.x);
            ffma2(acc[i][3], a2p, c23.y);
        }
    }
    #pragma unroll
    for (int i = 0; i < 8; i++) {
        size_t base = (size_t)(b0 + ty * 8 + i) * CDIM + c0 + tx * 8;
        uint4 pk;
        __half2 h0 = __float22half2_rn(unpack2(acc[i][0]));
        __half2 h1 = __float22half2_rn(unpack2(acc[i][1]));
        __half2 h2 = __float22half2_rn(unpack2(acc[i][2]));
        __half2 h3 = __float22half2_rn(unpack2(acc[i][3]));
        pk.x = *(unsigned int*)&h0;
        pk.y = *(unsigned int*)&h1;
        pk.z = *(unsigned int*)&h2;
        pk.w = *(unsigned int*)&h3;
        *(uint4*)&g_qWh[base] = pk;
    }
}

// ---------------- K3: gather + logits + softmax + feature mix (fp16 out) ----------
__global__ void __launch_bounds__(256) k_attn(const int* __restrict__ vidx,
                                              const float* __restrict__ feats_g,
                                              const float* __restrict__ scores_g,
                                              const int* __restrict__ camids,
                                              const float* __restrict__ extr) {
    __shared__ float sf[MVIEW][FDIM];       // 12 KB gathered features
    __shared__ float sqw[CDIM];             // 8.7 KB (fp32, converted on load)
    __shared__ float sext[MVIEW][16];
    __shared__ float sp[HEADS][MVIEW];
    __shared__ float smask[MVIEW];
    __shared__ int   scam[MVIEW];

    int b = blockIdx.x;
    int tid = threadIdx.x;
    int idx = vidx[b];

    const float4* fsrc = (const float4*)(feats_g + (size_t)idx * MVIEW * FDIM);
    float4* fdst = (float4*)&sf[0][0];
    for (int i = tid; i < MVIEW * FDIM / 4; i += 256) fdst[i] = fsrc[i];

    const __half2* qsrc = (const __half2*)(g_qWh + (size_t)b * CDIM);
    for (int i = tid; i < CDIM / 2; i += 256) {
        float2 f = __half22float2(qsrc[i]);
        *(float2*)&sqw[2 * i] = f;
    }

    if (tid < MVIEW) {
        float s = scores_g[(size_t)idx * MVIEW + tid];
        smask[tid] = (s < 0.0f) ? -1e30f : 0.0f;
        scam[tid] = camids[(size_t)idx * MVIEW + tid];
    }
    __syncthreads();
    if (tid < MVIEW * 16) {
        int m = tid >> 4, j = tid & 15;
        sext[m][j] = extr[scam[m] * 16 + j];
    }
    __syncthreads();

    // head w handled by warp w
    int w = tid >> 5, lane = tid & 31;
    float lg[MVIEW];
    #pragma unroll
    for (int m = 0; m < MVIEW; m++) {
        float s = 0.0f;
        #pragma unroll
        for (int u = 0; u < 8; u++) {
            int t = lane + u * 32;
            s += sf[m][t] * sqw[w * FAUG + t];
        }
        if (lane < 16) s += sext[m][lane] * sqw[w * FAUG + 256 + lane];
        #pragma unroll
        for (int o = 16; o > 0; o >>= 1) s += __shfl_xor_sync(0xffffffffu, s, o);
        lg[m] = s * 0.125f + smask[m];   // valid on lane 0
    }
    if (lane == 0) {
        float mx = -FLT_MAX;
        #pragma unroll
        for (int m = 0; m < MVIEW; m++) mx = fmaxf(mx, lg[m]);
        float e[MVIEW], sum = 0.0f;
        #pragma unroll
        for (int m = 0; m < MVIEW; m++) { e[m] = __expf(lg[m] - mx); sum += e[m]; }
        float inv = 1.0f / sum;
        #pragma unroll
        for (int m = 0; m < MVIEW; m++) sp[w][m] = e[m] * inv;
    }
    __syncthreads();

    // mixed[b,h,t] = sum_m p[h,m]*feats[m,t]; thread owns 2 adjacent t, 4 heads.
    int part = tid >> 7;            // 0..1
    int t2 = (tid & 127) * 2;       // even column
    float2 fv2[MVIEW];
    #pragma unroll
    for (int m = 0; m < MVIEW; m++) fv2[m] = *(float2*)&sf[m][t2];
    #pragma unroll
    for (int hh = 0; hh < 4; hh++) {
        int h = hh * 2 + part;
        float a0 = 0.0f, a1 = 0.0f;
        #pragma unroll
        for (int m = 0; m < MVIEW; m++) {
            float p = sp[h][m];
            a0 += p * fv2[m].x;
            a1 += p * fv2[m].y;
        }
        *(__half2*)&g_mixedh[((size_t)b * HEADS + h) * FDIM + t2] =
            __floats2half2_rn(a0, a1);
    }
}

// ---------------- K4: out = mixedh @ Wvt (HMMA m16n8k16) ----------------
#define LDA 264   // 256 + 8 halfs padding (16B), keeps 16B alignment per row
#define OUT_SMEM_H ((128 * LDA + 64 * LDA) * 2)
__global__ void __launch_bounds__(256) k_out_hmma(float* __restrict__ out) {
    extern __shared__ __half smh[];
    __half* Ah = smh;               // [128][LDA]  mixed rows
    __half* Bt = smh + 128 * LDA;   // [64][LDA]   Wv_h transposed (n-major, k inner)
    int h = blockIdx.y;
    int b0 = blockIdx.x * 128;
    int tid = threadIdx.x;

    for (int i = tid; i < 128 * 32; i += 256) {
        int r = i >> 5, c8 = (i & 31) * 8;
        *(uint4*)&Ah[r * LDA + c8] =
            *(const uint4*)&g_mixedh[((size_t)(b0 + r) * HEADS + h) * FDIM + c8];
    }
    for (int i = tid; i < 64 * 32; i += 256) {
        int r = i >> 5, c8 = (i & 31) * 8;
        *(uint4*)&Bt[r * LDA + c8] =
            *(const uint4*)&g_Wvt[(size_t)(h * 64 + r) * FDIM + c8];
    }
    __syncthreads();

    int w = tid >> 5, lane = tid & 31;
    int m0 = w * 16;
    float acc[8][4] = {};

    unsigned aBase = su32(Ah + (m0 + (lane & 15)) * LDA + (lane >> 4) * 8);
    unsigned bBase = su32(Bt + (lane & 7) * LDA + ((lane >> 3) & 1) * 8);

    #pragma unroll
    for (int ks = 0; ks < 16; ks++) {
        unsigned a0, a1, a2, a3;
        asm volatile(
            "ldmatrix.sync.aligned.m8n8.x4.shared.b16 {%0,%1,%2,%3}, [%4];"
            : "=r"(a0), "=r"(a1), "=r"(a2), "=r"(a3)
            : "r"(aBase + ks * 32));
        #pragma unroll
        for (int nf = 0; nf < 8; nf++) {
            unsigned br0, br1;
            asm volatile(
                "ldmatrix.sync.aligned.m8n8.x2.shared.b16 {%0,%1}, [%2];"
                : "=r"(br0), "=r"(br1)
                : "r"(bBase + (unsigned)(nf * 8 * LDA * 2) + ks * 32));
            asm volatile(
                "mma.sync.aligned.m16n8k16.row.col.f32.f16.f16.f32 "
                "{%0,%1,%2,%3},{%4,%5,%6,%7},{%8,%9},{%0,%1,%2,%3};"
                : "+f"(acc[nf][0]), "+f"(acc[nf][1]),
                  "+f"(acc[nf][2]), "+f"(acc[nf][3])
                : "r"(a0), "r"(a1), "r"(a2), "r"(a3), "r"(br0), "r"(br1));
        }
    }

    int g = lane >> 2, tg = lane & 3;
    #pragma unroll
    for (int nf = 0; nf < 8; nf++) {
        size_t r = (size_t)(b0 + m0 + g);
        int col = h * 64 + nf * 8 + 2 * tg;
        *(float2*)&out[r * ODIM + col]       = make_float2(acc[nf][0], acc[nf][1]);
        *(float2*)&out[(r + 8) * ODIM + col] = make_float2(acc[nf][2], acc[nf][3]);
    }
}

// ---------------- launcher ----------------
extern "C" void kernel_launch(void* const* d_in, const int* in_sizes, int n_in,
                              void* d_out, int out_size) {
    const int*   vidx = (const int*)d_in[0];    // vox_indices (B,)
    const float* vox  = (const float*)d_in[1];  // voxels (N_VOX,3)
    const float* vf   = (const float*)d_in[2];  // voxel_features (N_VOX,12,256)
    const float* vs   = (const float*)d_in[3];  // voxel_feature_scores (N_VOX,12)
    const int*   cam  = (const int*)d_in[4];    // camera_ids (N_VOX,12)
    const float* ext  = (const float*)d_in[5];  // extrinsics (48,16)
    const float* Wq   = (const float*)d_in[6];  // (24,512)
    const float* Wk   = (const float*)d_in[7];  // (272,512)
    const float* Wv   = (const float*)d_in[8];  // (256,512)
    float* out = (float*)d_out;

    cudaFuncSetAttribute(k_out_hmma, cudaFuncAttributeMaxDynamicSharedMemorySize,
                         OUT_SMEM_H);

    k_prep<<<(PE3 * CDIM + ODIM * FDIM + 255) / 256, 256>>>(Wq, Wk, Wv);
    k_minmax<<<1, 1024>>>(vox);
    k_qw2<<<dim3(CDIM / 128, B_TOT / 128), 256>>>(vidx, vox);
    k_attn<<<B_TOT, 256>>>(vidx, vf, vs, cam, ext);
    k_out_hmma<<<dim3(B_TOT / 128, HEADS), 256, OUT_SMEM_H>>>(out);
}

// round 8
// speedup vs baseline: 2.5271x; 1.0396x over previous
#include <cuda_runtime.h>
#include <cuda_fp16.h>
#include <math.h>
#include <float.h>

#define B_TOT   16384
#define NVOX    50000
#define MVIEW   12
#define FDIM    256
#define FAUG    272       // FDIM + 16 (extrinsics)
#define HEADS   8
#define QDIM    512       // HEADS*DK
#define ODIM    512       // HEADS*DV
#define PE3     24        // PE_ORDER*3
#define CDIM    2176      // HEADS*FAUG

// ---------------- scratch (static device memory; no allocation) ----------------
__device__ float  g_mn[3];
__device__ float  g_rinv[3];
__device__ float  g_C2[PE3 * CDIM];                        // 209 KB
__device__ __half g_qWh[(size_t)B_TOT * CDIM];             // 71 MB
__device__ __half g_mixedh[(size_t)B_TOT * HEADS * FDIM];  // 67 MB
__device__ __half g_Wvt[ODIM * FDIM];                      // 512 KB  [h*64+n][k]

// ---------------- packed f32x2 helpers ----------------
__device__ __forceinline__ void ffma2(unsigned long long& d,
                                      unsigned long long a,
                                      unsigned long long b) {
    asm("fma.rn.f32x2 %0, %1, %2, %0;" : "+l"(d) : "l"(a), "l"(b));
}
__device__ __forceinline__ unsigned long long pack2(float x, float y) {
    unsigned long long r;
    asm("mov.b64 %0, {%1, %2};" : "=l"(r) : "f"(x), "f"(y));
    return r;
}
__device__ __forceinline__ float2 unpack2(unsigned long long v) {
    float2 r;
    asm("mov.b64 {%0, %1}, %2;" : "=f"(r.x), "=f"(r.y) : "l"(v));
    return r;
}
__device__ __forceinline__ unsigned su32(const void* p) {
    return (unsigned)__cvta_generic_to_shared(p);
}

// ---------------- K0: fused C2 + Wv transpose prep ----------------
__global__ void __launch_bounds__(256) k_prep(const float* __restrict__ Wq,
                                              const float* __restrict__ Wk,
                                              const float* __restrict__ Wv) {
    int i = blockIdx.x * 256 + threadIdx.x;
    if (i < PE3 * CDIM) {
        int j = i / CDIM;
        int col = i - j * CDIM;
        int h = col / FAUG;
        int f = col - h * FAUG;
        const float4* wq = (const float4*)(Wq + j * QDIM + h * 64);
        const float4* wk = (const float4*)(Wk + (size_t)f * QDIM + h * 64);
        float a0 = 0.f, a1 = 0.f, a2 = 0.f, a3 = 0.f;
        #pragma unroll
        for (int d = 0; d < 16; d++) {
            float4 q = wq[d], k = wk[d];
            a0 += q.x * k.x; a1 += q.y * k.y;
            a2 += q.z * k.z; a3 += q.w * k.w;
        }
        g_C2[i] = (a0 + a1) + (a2 + a3);
    } else {
        int t = i - PE3 * CDIM;
        if (t < ODIM * FDIM) {
            int r = t >> 8, k = t & 255;
            g_Wvt[t] = __float2half(Wv[(size_t)k * ODIM + r]);
        }
    }
}

// ---------------- K1: single-block min/max ----------------
__global__ void __launch_bounds__(1024) k_minmax(const float* __restrict__ vox) {
    __shared__ float red[32][6];
    int tid = threadIdx.x;
    float mn[3] = {FLT_MAX, FLT_MAX, FLT_MAX};
    float mx[3] = {-FLT_MAX, -FLT_MAX, -FLT_MAX};
    for (int r = tid; r < NVOX; r += 1024) {
        #pragma unroll
        for (int c = 0; c < 3; c++) {
            float v = vox[r * 3 + c];
            mn[c] = fminf(mn[c], v);
            mx[c] = fmaxf(mx[c], v);
        }
    }
    #pragma unroll
    for (int c = 0; c < 3; c++) {
        #pragma unroll
        for (int o = 16; o > 0; o >>= 1) {
            mn[c] = fminf(mn[c], __shfl_xor_sync(0xffffffffu, mn[c], o));
            mx[c] = fmaxf(mx[c], __shfl_xor_sync(0xffffffffu, mx[c], o));
        }
    }
    if ((tid & 31) == 0) {
        #pragma unroll
        for (int c = 0; c < 3; c++) {
            red[tid >> 5][c]     = mn[c];
            red[tid >> 5][3 + c] = mx[c];
        }
    }
    __syncthreads();
    if (tid < 32) {
        #pragma unroll
        for (int c = 0; c < 3; c++) { mn[c] = red[tid][c]; mx[c] = red[tid][3 + c]; }
        #pragma unroll
        for (int c = 0; c < 3; c++) {
            #pragma unroll
            for (int o = 16; o > 0; o >>= 1) {
                mn[c] = fminf(mn[c], __shfl_xor_sync(0xffffffffu, mn[c], o));
                mx[c] = fmaxf(mx[c], __shfl_xor_sync(0xffffffffu, mx[c], o));
            }
        }
        if (tid < 3) {
            g_mn[tid] = mn[tid];
            g_rinv[tid] = 1.0f / (mx[tid] - mn[tid]);
        }
    }
}

// ---------------- K2: qW = PE(xyz) @ C2  (pe computed in-kernel) ----------------
__global__ void __launch_bounds__(256) k_qw2(const int* __restrict__ vidx,
                                             const float* __restrict__ vox) {
    __shared__ float peS[PE3][132];   // [k][row], padded
    __shared__ float c2S[PE3][132];   // [k][col], padded
    int b0 = blockIdx.y * 128;
    int c0 = blockIdx.x * 128;
    int tid = threadIdx.x;

    if (tid < 128) {
        int idx = vidx[b0 + tid];
        float xn[3];
        #pragma unroll
        for (int c = 0; c < 3; c++)
            xn[c] = (vox[idx * 3 + c] - g_mn[c]) * g_rinv[c] - 0.5f;
        float fr = 1.0f;
        #pragma unroll
        for (int p = 0; p < 8; p++) {
            peS[p * 3 + 0][tid] = sinf(xn[0] * fr);
            peS[p * 3 + 1][tid] = sinf(xn[1] * fr);
            peS[p * 3 + 2][tid] = sinf(xn[2] * fr);
            fr *= 2.0f;
        }
    }
    for (int i = tid; i < PE3 * 128; i += 256) {
        int j = i >> 7, c = i & 127;
        c2S[j][c] = g_C2[j * CDIM + c0 + c];
    }
    __syncthreads();

    int ty = tid >> 4, tx = tid & 15;
    unsigned long long acc[8][4] = {};
    #pragma unroll
    for (int k = 0; k < PE3; k++) {
        float a[8];
        *(float4*)&a[0] = *(float4*)&peS[k][ty * 8];
        *(float4*)&a[4] = *(float4*)&peS[k][ty * 8 + 4];
        ulonglong2 c01 = *(ulonglong2*)&c2S[k][tx * 8];
        ulonglong2 c23 = *(ulonglong2*)&c2S[k][tx * 8 + 4];
        #pragma unroll
        for (int i = 0; i < 8; i++) {
            unsigned long long a2p = pack2(a[i], a[i]);
            ffma2(acc[i][0], a2p, c01.x);
            ffma2(acc[i][1], a2p, c01.y);
            ffma2(acc[i][2], a2p, c23.x);
            ffma2(acc[i][3], a2p, c23.y);
        }
    }
    #pragma unroll
    for (int i = 0; i < 8; i++) {
        size_t base = (size_t)(b0 + ty * 8 + i) * CDIM + c0 + tx * 8;
        uint4 pk;
        __half2 h0 = __float22half2_rn(unpack2(acc[i][0]));
        __half2 h1 = __float22half2_rn(unpack2(acc[i][1]));
        __half2 h2 = __float22half2_rn(unpack2(acc[i][2]));
        __half2 h3 = __float22half2_rn(unpack2(acc[i][3]));
        pk.x = *(unsigned int*)&h0;
        pk.y = *(unsigned int*)&h1;
        pk.z = *(unsigned int*)&h2;
        pk.w = *(unsigned int*)&h3;
        *(uint4*)&g_qWh[base] = pk;
    }
}

// ---------------- K3: gather + logits + softmax + feature mix ----------------
// Logits read fp16 copies (sfh, sqwh) — half the LDS bytes, 1/4 the LDS instrs.
// Mix reads the fp32 tile (sf) to protect output precision.
__global__ void __launch_bounds__(256) k_attn(const int* __restrict__ vidx,
                                              const float* __restrict__ feats_g,
                                              const float* __restrict__ scores_g,
                                              const int* __restrict__ camids,
                                              const float* __restrict__ extr) {
    __shared__ float  sf[MVIEW][FDIM];      // 12 KB fp32 features (mix phase)
    __shared__ __half sfh[MVIEW][FDIM];     // 6 KB fp16 features (logits)
    __shared__ __half sqwh[HEADS][FDIM];    // 4 KB qW main part
    __shared__ float  sqwe[HEADS][16];      // ext tail of qW (fp32)
    __shared__ float  sext[MVIEW][16];
    __shared__ float  sp[HEADS][MVIEW];
    __shared__ float  smask[MVIEW];
    __shared__ int    scam[MVIEW];

    int b = blockIdx.x;
    int tid = threadIdx.x;
    int idx = vidx[b];

    // gather features: fp32 tile + fp16 shadow
    const float4* fsrc = (const float4*)(feats_g + (size_t)idx * MVIEW * FDIM);
    #pragma unroll
    for (int ii = 0; ii < 3; ii++) {
        int i = tid + ii * 256;
        float4 v = fsrc[i];
        ((float4*)&sf[0][0])[i] = v;
        __half2 lo = __floats2half2_rn(v.x, v.y);
        __half2 hi = __floats2half2_rn(v.z, v.w);
        unsigned int pk0 = *(unsigned int*)&lo, pk1 = *(unsigned int*)&hi;
        ((uint2*)&sfh[0][0])[i] = make_uint2(pk0, pk1);
    }

    // qW: 136 half2 per head; first 128 stay fp16, last 8 convert to fp32 ext
    const __half2* qsrc = (const __half2*)(g_qWh + (size_t)b * CDIM);
    for (int i = tid; i < HEADS * 136; i += 256) {
        int h = i / 136, j = i - h * 136;
        __half2 v = qsrc[h * 136 + j];
        if (j < 128) {
            *(__half2*)&sqwh[h][2 * j] = v;
        } else {
            int jj = j - 128;
            float2 f = __half22float2(v);
            sqwe[h][2 * jj]     = f.x;
            sqwe[h][2 * jj + 1] = f.y;
        }
    }

    if (tid < MVIEW) {
        float s = scores_g[(size_t)idx * MVIEW + tid];
        smask[tid] = (s < 0.0f) ? -1e30f : 0.0f;
        scam[tid] = camids[(size_t)idx * MVIEW + tid];
    }
    __syncthreads();
    if (tid < MVIEW * 16) {
        int m = tid >> 4, j = tid & 15;
        sext[m][j] = extr[scam[m] * 16 + j];
    }
    __syncthreads();

    // ---- logits: head w = warp w; lane owns 8 contiguous t ----
    int w = tid >> 5, lane = tid & 31;
    float qvf[8];
    {
        uint4 qr = *(uint4*)&sqwh[w][lane * 8];
        float2 q0 = __half22float2(*(__half2*)&qr.x);
        float2 q1 = __half22float2(*(__half2*)&qr.y);
        float2 q2 = __half22float2(*(__half2*)&qr.z);
        float2 q3 = __half22float2(*(__half2*)&qr.w);
        qvf[0] = q0.x; qvf[1] = q0.y; qvf[2] = q1.x; qvf[3] = q1.y;
        qvf[4] = q2.x; qvf[5] = q2.y; qvf[6] = q3.x; qvf[7] = q3.y;
    }
    float qe = (lane < 16) ? sqwe[w][lane] : 0.0f;

    float lg[MVIEW];
    #pragma unroll
    for (int m = 0; m < MVIEW; m++) {
        uint4 raw = *(uint4*)&sfh[m][lane * 8];
        float2 f0 = __half22float2(*(__half2*)&raw.x);
        float2 f1 = __half22float2(*(__half2*)&raw.y);
        float2 f2 = __half22float2(*(__half2*)&raw.z);
        float2 f3 = __half22float2(*(__half2*)&raw.w);
        float s = qvf[0] * f0.x + qvf[1] * f0.y
                + qvf[2] * f1.x + qvf[3] * f1.y
                + qvf[4] * f2.x + qvf[5] * f2.y
                + qvf[6] * f3.x + qvf[7] * f3.y;
        if (lane < 16) s += sext[m][lane] * qe;
        #pragma unroll
        for (int o = 16; o > 0; o >>= 1) s += __shfl_xor_sync(0xffffffffu, s, o);
        lg[m] = s * 0.125f + smask[m];
    }
    if (lane == 0) {
        float mx = -FLT_MAX;
        #pragma unroll
        for (int m = 0; m < MVIEW; m++) mx = fmaxf(mx, lg[m]);
        float e[MVIEW], sum = 0.0f;
        #pragma unroll
        for (int m = 0; m < MVIEW; m++) { e[m] = __expf(lg[m] - mx); sum += e[m]; }
        float inv = 1.0f / sum;
        #pragma unroll
        for (int m = 0; m < MVIEW; m++) sp[w][m] = e[m] * inv;
    }
    __syncthreads();

    // ---- mix: thread owns 2 adjacent t, 4 heads; fp32 feats ----
    int part = tid >> 7;
    int t2 = (tid & 127) * 2;
    float2 fv2[MVIEW];
    #pragma unroll
    for (int m = 0; m < MVIEW; m++) fv2[m] = *(float2*)&sf[m][t2];
    #pragma unroll
    for (int hh = 0; hh < 4; hh++) {
        int h = hh * 2 + part;
        float a0 = 0.0f, a1 = 0.0f;
        #pragma unroll
        for (int m = 0; m < MVIEW; m++) {
            float p = sp[h][m];
            a0 += p * fv2[m].x;
            a1 += p * fv2[m].y;
        }
        *(__half2*)&g_mixedh[((size_t)b * HEADS + h) * FDIM + t2] =
            __floats2half2_rn(a0, a1);
    }
}

// ---------------- K4: out = mixedh @ Wvt (HMMA m16n8k16) ----------------
#define LDA 264
#define OUT_SMEM_H ((128 * LDA + 64 * LDA) * 2)
__global__ void __launch_bounds__(256) k_out_hmma(float* __restrict__ out) {
    extern __shared__ __half smh[];
    __half* Ah = smh;
    __half* Bt = smh + 128 * LDA;
    int h = blockIdx.y;
    int b0 = blockIdx.x * 128;
    int tid = threadIdx.x;

    for (int i = tid; i < 128 * 32; i += 256) {
        int r = i >> 5, c8 = (i & 31) * 8;
        *(uint4*)&Ah[r * LDA + c8] =
            *(const uint4*)&g_mixedh[((size_t)(b0 + r) * HEADS + h) * FDIM + c8];
    }
    for (int i = tid; i < 64 * 32; i += 256) {
        int r = i >> 5, c8 = (i & 31) * 8;
        *(uint4*)&Bt[r * LDA + c8] =
            *(const uint4*)&g_Wvt[(size_t)(h * 64 + r) * FDIM + c8];
    }
    __syncthreads();

    int w = tid >> 5, lane = tid & 31;
    int m0 = w * 16;
    float acc[8][4] = {};

    unsigned aBase = su32(Ah + (m0 + (lane & 15)) * LDA + (lane >> 4) * 8);
    unsigned bBase = su32(Bt + (lane & 7) * LDA + ((lane >> 3) & 1) * 8);

    #pragma unroll
    for (int ks = 0; ks < 16; ks++) {
        unsigned a0, a1, a2, a3;
        asm volatile(
            "ldmatrix.sync.aligned.m8n8.x4.shared.b16 {%0,%1,%2,%3}, [%4];"
            : "=r"(a0), "=r"(a1), "=r"(a2), "=r"(a3)
            : "r"(aBase + ks * 32));
        #pragma unroll
        for (int nf = 0; nf < 8; nf++) {
            unsigned br0, br1;
            asm volatile(
                "ldmatrix.sync.aligned.m8n8.x2.shared.b16 {%0,%1}, [%2];"
                : "=r"(br0), "=r"(br1)
                : "r"(bBase + (unsigned)(nf * 8 * LDA * 2) + ks * 32));
            asm volatile(
                "mma.sync.aligned.m16n8k16.row.col.f32.f16.f16.f32 "
                "{%0,%1,%2,%3},{%4,%5,%6,%7},{%8,%9},{%0,%1,%2,%3};"
                : "+f"(acc[nf][0]), "+f"(acc[nf][1]),
                  "+f"(acc[nf][2]), "+f"(acc[nf][3])
                : "r"(a0), "r"(a1), "r"(a2), "r"(a3), "r"(br0), "r"(br1));
        }
    }

    int g = lane >> 2, tg = lane & 3;
    #pragma unroll
    for (int nf = 0; nf < 8; nf++) {
        size_t r = (size_t)(b0 + m0 + g);
        int col = h * 64 + nf * 8 + 2 * tg;
        *(float2*)&out[r * ODIM + col]       = make_float2(acc[nf][0], acc[nf][1]);
        *(float2*)&out[(r + 8) * ODIM + col] = make_float2(acc[nf][2], acc[nf][3]);
    }
}

// ---------------- launcher ----------------
extern "C" void kernel_launch(void* const* d_in, const int* in_sizes, int n_in,
                              void* d_out, int out_size) {
    const int*   vidx = (const int*)d_in[0];
    const float* vox  = (const float*)d_in[1];
    const float* vf   = (const float*)d_in[2];
    const float* vs   = (const float*)d_in[3];
    const int*   cam  = (const int*)d_in[4];
    const float* ext  = (const float*)d_in[5];
    const float* Wq   = (const float*)d_in[6];
    const float* Wk   = (const float*)d_in[7];
    const float* Wv   = (const float*)d_in[8];
    float* out = (float*)d_out;

    cudaFuncSetAttribute(k_out_hmma, cudaFuncAttributeMaxDynamicSharedMemorySize,
                         OUT_SMEM_H);

    k_prep<<<(PE3 * CDIM + ODIM * FDIM + 255) / 256, 256>>>(Wq, Wk, Wv);
    k_minmax<<<1, 1024>>>(vox);
    k_qw2<<<dim3(CDIM / 128, B_TOT / 128), 256>>>(vidx, vox);
    k_attn<<<B_TOT, 256>>>(vidx, vf, vs, cam, ext);
    k_out_hmma<<<dim3(B_TOT / 128, HEADS), 256, OUT_SMEM_H>>>(out);
}

// round 9
// speedup vs baseline: 2.8019x; 1.1088x over previous
#include <cuda_runtime.h>
#include <cuda_fp16.h>
#include <math.h>
#include <float.h>

#define B_TOT   16384
#define NVOX    50000
#define MVIEW   12
#define FDIM    256
#define FAUG    272       // FDIM + 16 (extrinsics)
#define HEADS   8
#define QDIM    512       // HEADS*DK
#define ODIM    512       // HEADS*DV
#define PE3     24        // PE_ORDER*3
#define CDIM    2176      // HEADS*FAUG

// ---------------- scratch (static device memory; no allocation) ----------------
__device__ float  g_mn[3];
__device__ float  g_rinv[3];
__device__ float  g_C2[PE3 * CDIM];                        // 209 KB
__device__ __half g_qWh[(size_t)B_TOT * CDIM];             // 71 MB
__device__ __half g_mixedh[(size_t)B_TOT * HEADS * FDIM];  // 67 MB
__device__ __half g_Wvt[ODIM * FDIM];                      // 512 KB  [h*64+n][k]

__device__ __forceinline__ unsigned su32(const void* p) {
    return (unsigned)__cvta_generic_to_shared(p);
}

// ---------------- K0: fused C2 + Wv transpose prep ----------------
__global__ void __launch_bounds__(256) k_prep(const float* __restrict__ Wq,
                                              const float* __restrict__ Wk,
                                              const float* __restrict__ Wv) {
    int i = blockIdx.x * 256 + threadIdx.x;
    if (i < PE3 * CDIM) {
        int j = i / CDIM;
        int col = i - j * CDIM;
        int h = col / FAUG;
        int f = col - h * FAUG;
        const float4* wq = (const float4*)(Wq + j * QDIM + h * 64);
        const float4* wk = (const float4*)(Wk + (size_t)f * QDIM + h * 64);
        float a0 = 0.f, a1 = 0.f, a2 = 0.f, a3 = 0.f;
        #pragma unroll
        for (int d = 0; d < 16; d++) {
            float4 q = wq[d], k = wk[d];
            a0 += q.x * k.x; a1 += q.y * k.y;
            a2 += q.z * k.z; a3 += q.w * k.w;
        }
        g_C2[i] = (a0 + a1) + (a2 + a3);
    } else {
        int t = i - PE3 * CDIM;
        if (t < ODIM * FDIM) {
            int r = t >> 8, k = t & 255;
            g_Wvt[t] = __float2half(Wv[(size_t)k * ODIM + r]);
        }
    }
}

// ---------------- K1: single-block min/max ----------------
__global__ void __launch_bounds__(1024) k_minmax(const float* __restrict__ vox) {
    __shared__ float red[32][6];
    int tid = threadIdx.x;
    float mn[3] = {FLT_MAX, FLT_MAX, FLT_MAX};
    float mx[3] = {-FLT_MAX, -FLT_MAX, -FLT_MAX};
    for (int r = tid; r < NVOX; r += 1024) {
        #pragma unroll
        for (int c = 0; c < 3; c++) {
            float v = vox[r * 3 + c];
            mn[c] = fminf(mn[c], v);
            mx[c] = fmaxf(mx[c], v);
        }
    }
    #pragma unroll
    for (int c = 0; c < 3; c++) {
        #pragma unroll
        for (int o = 16; o > 0; o >>= 1) {
            mn[c] = fminf(mn[c], __shfl_xor_sync(0xffffffffu, mn[c], o));
            mx[c] = fmaxf(mx[c], __shfl_xor_sync(0xffffffffu, mx[c], o));
        }
    }
    if ((tid & 31) == 0) {
        #pragma unroll
        for (int c = 0; c < 3; c++) {
            red[tid >> 5][c]     = mn[c];
            red[tid >> 5][3 + c] = mx[c];
        }
    }
    __syncthreads();
    if (tid < 32) {
        #pragma unroll
        for (int c = 0; c < 3; c++) { mn[c] = red[tid][c]; mx[c] = red[tid][3 + c]; }
        #pragma unroll
        for (int c = 0; c < 3; c++) {
            #pragma unroll
            for (int o = 16; o > 0; o >>= 1) {
                mn[c] = fminf(mn[c], __shfl_xor_sync(0xffffffffu, mn[c], o));
                mx[c] = fmaxf(mx[c], __shfl_xor_sync(0xffffffffu, mx[c], o));
            }
        }
        if (tid < 3) {
            g_mn[tid] = mn[tid];
            g_rinv[tid] = 1.0f / (mx[tid] - mn[tid]);
        }
    }
}

// ---------------- K2: qW = PE(xyz) @ C2 via HMMA (K padded 24->32) --------------
// Tile: 128 rows x 128 cols per CTA; warp w -> 16 rows x 128 cols.
#define QLD 40   // halfs per smem row (80 B, 16B-aligned)
__global__ void __launch_bounds__(256) k_qw2h(const int* __restrict__ vidx,
                                              const float* __restrict__ vox) {
    __shared__ __half Ah[128 * QLD];  // [row][k]  pe fp16, k 24..31 zero
    __shared__ __half Bh[128 * QLD];  // [col][k]  C2^T fp16
    int b0 = blockIdx.y * 128;
    int c0 = blockIdx.x * 128;
    int tid = threadIdx.x;

    if (tid < 128) {
        int idx = vidx[b0 + tid];
        float xn[3];
        #pragma unroll
        for (int c = 0; c < 3; c++)
            xn[c] = (vox[idx * 3 + c] - g_mn[c]) * g_rinv[c] - 0.5f;
        __half* ar = Ah + tid * QLD;
        float fr = 1.0f;
        #pragma unroll
        for (int p = 0; p < 8; p++) {
            ar[p * 3 + 0] = __float2half(sinf(xn[0] * fr));
            ar[p * 3 + 1] = __float2half(sinf(xn[1] * fr));
            ar[p * 3 + 2] = __float2half(sinf(xn[2] * fr));
            fr *= 2.0f;
        }
        #pragma unroll
        for (int k = PE3; k < 32; k++) ar[k] = __ushort_as_half(0);
    }
    for (int i = tid; i < 32 * 128; i += 256) {
        int k = i >> 7, c = i & 127;
        float v = (k < PE3) ? g_C2[k * CDIM + c0 + c] : 0.0f;
        Bh[c * QLD + k] = __float2half(v);
    }
    __syncthreads();

    int w = tid >> 5, lane = tid & 31;
    int m0 = w * 16;
    float acc[16][4] = {};

    unsigned aBase = su32(Ah + (m0 + (lane & 15)) * QLD + (lane >> 4) * 8);
    unsigned bBase = su32(Bh + (lane & 7) * QLD + ((lane >> 3) & 1) * 8);

    #pragma unroll
    for (int ks = 0; ks < 2; ks++) {
        unsigned a0, a1, a2, a3;
        asm volatile(
            "ldmatrix.sync.aligned.m8n8.x4.shared.b16 {%0,%1,%2,%3}, [%4];"
            : "=r"(a0), "=r"(a1), "=r"(a2), "=r"(a3)
            : "r"(aBase + ks * 32));
        #pragma unroll
        for (int nf = 0; nf < 16; nf++) {
            unsigned br0, br1;
            asm volatile(
                "ldmatrix.sync.aligned.m8n8.x2.shared.b16 {%0,%1}, [%2];"
                : "=r"(br0), "=r"(br1)
                : "r"(bBase + (unsigned)(nf * 8 * QLD * 2) + ks * 32));
            asm volatile(
                "mma.sync.aligned.m16n8k16.row.col.f32.f16.f16.f32 "
                "{%0,%1,%2,%3},{%4,%5,%6,%7},{%8,%9},{%0,%1,%2,%3};"
                : "+f"(acc[nf][0]), "+f"(acc[nf][1]),
                  "+f"(acc[nf][2]), "+f"(acc[nf][3])
                : "r"(a0), "r"(a1), "r"(a2), "r"(a3), "r"(br0), "r"(br1));
        }
    }

    int g = lane >> 2, tg = lane & 3;
    #pragma unroll
    for (int nf = 0; nf < 16; nf++) {
        size_t r = (size_t)(b0 + m0 + g);
        int col = c0 + nf * 8 + 2 * tg;
        *(__half2*)&g_qWh[r * CDIM + col] =
            __floats2half2_rn(acc[nf][0], acc[nf][1]);
        *(__half2*)&g_qWh[(r + 8) * CDIM + col] =
            __floats2half2_rn(acc[nf][2], acc[nf][3]);
    }
}

// ---------------- K3: gather + logits + softmax + feature mix (all-fp16 tile) ----
__global__ void __launch_bounds__(256) k_attn(const int* __restrict__ vidx,
                                              const float* __restrict__ feats_g,
                                              const float* __restrict__ scores_g,
                                              const int* __restrict__ camids,
                                              const float* __restrict__ extr) {
    __shared__ __half sfh[MVIEW][FDIM];     // 6 KB fp16 features
    __shared__ __half sqwh[HEADS][FDIM];    // 4 KB qW main part
    __shared__ float  sqwe[HEADS][16];      // ext tail of qW (fp32)
    __shared__ float  sext[MVIEW][16];
    __shared__ float  sp[HEADS][MVIEW];
    __shared__ float  smask[MVIEW];
    __shared__ int    scam[MVIEW];

    int b = blockIdx.x;
    int tid = threadIdx.x;
    int idx = vidx[b];

    // gather features -> fp16 smem
    const float4* fsrc = (const float4*)(feats_g + (size_t)idx * MVIEW * FDIM);
    #pragma unroll
    for (int ii = 0; ii < 3; ii++) {
        int i = tid + ii * 256;
        float4 v = fsrc[i];
        __half2 lo = __floats2half2_rn(v.x, v.y);
        __half2 hi = __floats2half2_rn(v.z, v.w);
        ((uint2*)&sfh[0][0])[i] =
            make_uint2(*(unsigned int*)&lo, *(unsigned int*)&hi);
    }

    // qW: 136 half2 per head; first 128 stay fp16, last 8 convert to fp32 ext
    const __half2* qsrc = (const __half2*)(g_qWh + (size_t)b * CDIM);
    for (int i = tid; i < HEADS * 136; i += 256) {
        int h = i / 136, j = i - h * 136;
        __half2 v = qsrc[h * 136 + j];
        if (j < 128) {
            *(__half2*)&sqwh[h][2 * j] = v;
        } else {
            int jj = j - 128;
            float2 f = __half22float2(v);
            sqwe[h][2 * jj]     = f.x;
            sqwe[h][2 * jj + 1] = f.y;
        }
    }

    if (tid < MVIEW) {
        float s = scores_g[(size_t)idx * MVIEW + tid];
        smask[tid] = (s < 0.0f) ? -1e30f : 0.0f;
        scam[tid] = camids[(size_t)idx * MVIEW + tid];
    }
    __syncthreads();
    if (tid < MVIEW * 16) {
        int m = tid >> 4, j = tid & 15;
        sext[m][j] = extr[scam[m] * 16 + j];
    }
    __syncthreads();

    // ---- logits: head w = warp w; lane owns 8 contiguous t ----
    int w = tid >> 5, lane = tid & 31;
    float qvf[8];
    {
        uint4 qr = *(uint4*)&sqwh[w][lane * 8];
        float2 q0 = __half22float2(*(__half2*)&qr.x);
        float2 q1 = __half22float2(*(__half2*)&qr.y);
        float2 q2 = __half22float2(*(__half2*)&qr.z);
        float2 q3 = __half22float2(*(__half2*)&qr.w);
        qvf[0] = q0.x; qvf[1] = q0.y; qvf[2] = q1.x; qvf[3] = q1.y;
        qvf[4] = q2.x; qvf[5] = q2.y; qvf[6] = q3.x; qvf[7] = q3.y;
    }
    float qe = (lane < 16) ? sqwe[w][lane] : 0.0f;

    float lg[MVIEW];
    #pragma unroll
    for (int m = 0; m < MVIEW; m++) {
        uint4 raw = *(uint4*)&sfh[m][lane * 8];
        float2 f0 = __half22float2(*(__half2*)&raw.x);
        float2 f1 = __half22float2(*(__half2*)&raw.y);
        float2 f2 = __half22float2(*(__half2*)&raw.z);
        float2 f3 = __half22float2(*(__half2*)&raw.w);
        float s = qvf[0] * f0.x + qvf[1] * f0.y
                + qvf[2] * f1.x + qvf[3] * f1.y
                + qvf[4] * f2.x + qvf[5] * f2.y
                + qvf[6] * f3.x + qvf[7] * f3.y;
        if (lane < 16) s += sext[m][lane] * qe;
        #pragma unroll
        for (int o = 16; o > 0; o >>= 1) s += __shfl_xor_sync(0xffffffffu, s, o);
        lg[m] = s * 0.125f + smask[m];
    }
    if (lane == 0) {
        float mx = -FLT_MAX;
        #pragma unroll
        for (int m = 0; m < MVIEW; m++) mx = fmaxf(mx, lg[m]);
        float e[MVIEW], sum = 0.0f;
        #pragma unroll
        for (int m = 0; m < MVIEW; m++) { e[m] = __expf(lg[m] - mx); sum += e[m]; }
        float inv = 1.0f / sum;
        #pragma unroll
        for (int m = 0; m < MVIEW; m++) sp[w][m] = e[m] * inv;
    }
    __syncthreads();

    // ---- mix: thread owns 2 adjacent t, 4 heads; fp16 feats, fp32 accum ----
    int part = tid >> 7;
    int t2 = (tid & 127) * 2;
    float2 fv2[MVIEW];
    #pragma unroll
    for (int m = 0; m < MVIEW; m++)
        fv2[m] = __half22float2(*(__half2*)&sfh[m][t2]);
    #pragma unroll
    for (int hh = 0; hh < 4; hh++) {
        int h = hh * 2 + part;
        float a0 = 0.0f, a1 = 0.0f;
        #pragma unroll
        for (int m = 0; m < MVIEW; m++) {
            float p = sp[h][m];
            a0 += p * fv2[m].x;
            a1 += p * fv2[m].y;
        }
        *(__half2*)&g_mixedh[((size_t)b * HEADS + h) * FDIM + t2] =
            __floats2half2_rn(a0, a1);
    }
}

// ---------------- K4: out = mixedh @ Wvt (HMMA m16n8k16) ----------------
#define LDA 264
#define OUT_SMEM_H ((128 * LDA + 64 * LDA) * 2)
__global__ void __launch_bounds__(256) k_out_hmma(float* __restrict__ out) {
    extern __shared__ __half smh[];
    __half* Ah = smh;
    __half* Bt = smh + 128 * LDA;
    int h = blockIdx.y;
    int b0 = blockIdx.x * 128;
    int tid = threadIdx.x;

    for (int i = tid; i < 128 * 32; i += 256) {
        int r = i >> 5, c8 = (i & 31) * 8;
        *(uint4*)&Ah[r * LDA + c8] =
            *(const uint4*)&g_mixedh[((size_t)(b0 + r) * HEADS + h) * FDIM + c8];
    }
    for (int i = tid; i < 64 * 32; i += 256) {
        int r = i >> 5, c8 = (i & 31) * 8;
        *(uint4*)&Bt[r * LDA + c8] =
            *(const uint4*)&g_Wvt[(size_t)(h * 64 + r) * FDIM + c8];
    }
    __syncthreads();

    int w = tid >> 5, lane = tid & 31;
    int m0 = w * 16;
    float acc[8][4] = {};

    unsigned aBase = su32(Ah + (m0 + (lane & 15)) * LDA + (lane >> 4) * 8);
    unsigned bBase = su32(Bt + (lane & 7) * LDA + ((lane >> 3) & 1) * 8);

    #pragma unroll
    for (int ks = 0; ks < 16; ks++) {
        unsigned a0, a1, a2, a3;
        asm volatile(
            "ldmatrix.sync.aligned.m8n8.x4.shared.b16 {%0,%1,%2,%3}, [%4];"
            : "=r"(a0), "=r"(a1), "=r"(a2), "=r"(a3)
            : "r"(aBase + ks * 32));
        #pragma unroll
        for (int nf = 0; nf < 8; nf++) {
            unsigned br0, br1;
            asm volatile(
                "ldmatrix.sync.aligned.m8n8.x2.shared.b16 {%0,%1}, [%2];"
                : "=r"(br0), "=r"(br1)
                : "r"(bBase + (unsigned)(nf * 8 * LDA * 2) + ks * 32));
            asm volatile(
                "mma.sync.aligned.m16n8k16.row.col.f32.f16.f16.f32 "
                "{%0,%1,%2,%3},{%4,%5,%6,%7},{%8,%9},{%0,%1,%2,%3};"
                : "+f"(acc[nf][0]), "+f"(acc[nf][1]),
                  "+f"(acc[nf][2]), "+f"(acc[nf][3])
                : "r"(a0), "r"(a1), "r"(a2), "r"(a3), "r"(br0), "r"(br1));
        }
    }

    int g = lane >> 2, tg = lane & 3;
    #pragma unroll
    for (int nf = 0; nf < 8; nf++) {
        size_t r = (size_t)(b0 + m0 + g);
        int col = h * 64 + nf * 8 + 2 * tg;
        *(float2*)&out[r * ODIM + col]       = make_float2(acc[nf][0], acc[nf][1]);
        *(float2*)&out[(r + 8) * ODIM + col] = make_float2(acc[nf][2], acc[nf][3]);
    }
}

// ---------------- launcher ----------------
extern "C" void kernel_launch(void* const* d_in, const int* in_sizes, int n_in,
                              void* d_out, int out_size) {
    const int*   vidx = (const int*)d_in[0];
    const float* vox  = (const float*)d_in[1];
    const float* vf   = (const float*)d_in[2];
    const float* vs   = (const float*)d_in[3];
    const int*   cam  = (const int*)d_in[4];
    const float* ext  = (const float*)d_in[5];
    const float* Wq   = (const float*)d_in[6];
    const float* Wk   = (const float*)d_in[7];
    const float* Wv   = (const float*)d_in[8];
    float* out = (float*)d_out;

    cudaFuncSetAttribute(k_out_hmma, cudaFuncAttributeMaxDynamicSharedMemorySize,
                         OUT_SMEM_H);

    k_prep<<<(PE3 * CDIM + ODIM * FDIM + 255) / 256, 256>>>(Wq, Wk, Wv);
    k_minmax<<<1, 1024>>>(vox);
    k_qw2h<<<dim3(CDIM / 128, B_TOT / 128), 256>>>(vidx, vox);
    k_attn<<<B_TOT, 256>>>(vidx, vf, vs, cam, ext);
    k_out_hmma<<<dim3(B_TOT / 128, HEADS), 256, OUT_SMEM_H>>>(out);
}